// round 10
// baseline (speedup 1.0000x reference)
#include <cuda_runtime.h>
#include <cuda_bf16.h>
#include <cstdint>

// VQ-VAE quantizer: bf16-split HMMA (mma.sync) screening + exact-chain rescue,
// reproducing the JAX/XLA-CPU fp32 reference argmin bitwise.
//   x: [16, 256, 64, 64] f32   (d_in[0])
//   emb: [1024, 256] f32       (d_in[1])
//   out: [1 + 16*256*64*64] f32: out[0]=c_loss, out[1:]=quant_out (NCHW)

#define NUM_EMB 1024
#define EMB_DIM 256
#define HW 4096
#define NPIX 65536
#define KSPLIT 768              // [hi | hi | lo] x [hi | lo | hi]
#define MARGIN 1.5e-4f

__device__ double g_loss;
__device__ float g_enorm[NUM_EMB];
__device__ float g_xnorm[NPIX];
__device__ int g_idx[NPIX];
__device__ int g_resc_count;
__device__ int g_resc[NPIX];
__device__ __nv_bfloat16 g_Xp[(size_t)NPIX * KSPLIT];   // [pixel][768]
__device__ __nv_bfloat16 g_Ep[NUM_EMB * KSPLIT];        // [code][768]

#define MMA16816(d, a0, a1, a2, a3, bb0, bb1) \
    asm volatile("mma.sync.aligned.m16n8k16.row.col.f32.bf16.bf16.f32 " \
                 "{%0,%1,%2,%3}, {%4,%5,%6,%7}, {%8,%9}, {%0,%1,%2,%3};" \
                 : "+f"((d)[0]), "+f"((d)[1]), "+f"((d)[2]), "+f"((d)[3]) \
                 : "r"(a0), "r"(a1), "r"(a2), "r"(a3), "r"(bb0), "r"(bb1))

// ---------------- reference-rounding helpers ----------------
__device__ __forceinline__ float reduce8_pattern(const float S[8]) {
    float t02 = __fadd_rn(__fadd_rn(S[0], S[4]), __fadd_rn(S[2], S[6]));
    float t13 = __fadd_rn(__fadd_rn(S[1], S[5]), __fadd_rn(S[3], S[7]));
    return __fadd_rn(t02, t13);
}

// ---------------- kernel 1: init (zero accums, enorm, split E) ----------------
__global__ void vq_init_kernel(const float* __restrict__ emb) {
    int k = blockIdx.x * blockDim.x + threadIdx.x;
    if (k == 0) { g_loss = 0.0; g_resc_count = 0; }
    if (k < NUM_EMB) {
        const float* row = emb + (size_t)k * EMB_DIM;
        float S[8];
#pragma unroll
        for (int r = 0; r < 8; r++) S[r] = 0.f;
        for (int c = 0; c < EMB_DIM; c += 8)
#pragma unroll
            for (int r = 0; r < 8; r++) {
                float v = row[c + r];
                S[r] = __fadd_rn(S[r], __fmul_rn(v, v));
            }
        g_enorm[k] = reduce8_pattern(S);
        // split: Ep = [hi | lo | hi]
        __nv_bfloat16* er = g_Ep + (size_t)k * KSPLIT;
        for (int c = 0; c < EMB_DIM; c++) {
            float v = row[c];
            __nv_bfloat16 hi = __float2bfloat16_rn(v);
            __nv_bfloat16 lo = __float2bfloat16_rn(v - __bfloat162float(hi));
            er[c] = hi; er[256 + c] = lo; er[512 + c] = hi;
        }
    }
}

// ---------------- kernel 2: split X into [hi | hi | lo] row-major ----------------
__global__ __launch_bounds__(256)
void vq_xsplit_kernel(const float* __restrict__ x) {
    __shared__ float xs[128 * 66];   // [p][c], stride 66
    const int tid = threadIdx.x;
    const int pix0 = blockIdx.x * 128;
    const int b = pix0 >> 12;
    const int hw0 = pix0 & (HW - 1);
    const float* xbase = x + ((size_t)b * EMB_DIM) * HW + hw0;

    for (int c0 = 0; c0 < EMB_DIM; c0 += 64) {
        __syncthreads();
#pragma unroll
        for (int it = 0; it < 32; it++) {
            int i = tid + it * 256;
            int p = i & 127, c = i >> 7;
            xs[p * 66 + c] = xbase[(size_t)(c0 + c) * HW + p];
        }
        __syncthreads();
#pragma unroll
        for (int it = 0; it < 16; it++) {
            int i = tid + it * 256;
            int p = i >> 5, cp = i & 31;
            float2 v = *(const float2*)&xs[p * 66 + 2 * cp];
            __nv_bfloat16 h0 = __float2bfloat16_rn(v.x);
            __nv_bfloat16 l0 = __float2bfloat16_rn(v.x - __bfloat162float(h0));
            __nv_bfloat16 h1 = __float2bfloat16_rn(v.y);
            __nv_bfloat16 l1 = __float2bfloat16_rn(v.y - __bfloat162float(h1));
            size_t row = (size_t)(pix0 + p) * KSPLIT;
            __nv_bfloat162 hh; hh.x = h0; hh.y = h1;
            __nv_bfloat162 ll; ll.x = l0; ll.y = l1;
            *(__nv_bfloat162*)&g_Xp[row + c0 + 2 * cp] = hh;
            *(__nv_bfloat162*)&g_Xp[row + 256 + c0 + 2 * cp] = hh;
            *(__nv_bfloat162*)&g_Xp[row + 512 + c0 + 2 * cp] = ll;
        }
    }
}

// ---------------- kernel 3: per-pixel ||x||^2 with reference pattern ----------
__global__ __launch_bounds__(256)
void vq_xnorm_kernel(const float* __restrict__ x) {
    int p = blockIdx.x * 256 + threadIdx.x;
    int b = p >> 12;
    int hw = p & (HW - 1);
    const float* xb = x + ((size_t)b * EMB_DIM) * HW + hw;
    float S[8];
#pragma unroll
    for (int r = 0; r < 8; r++) S[r] = 0.f;
    for (int c = 0; c < EMB_DIM; c += 8)
#pragma unroll
        for (int r = 0; r < 8; r++) {
            float v = xb[(size_t)(c + r) * HW];
            S[r] = __fadd_rn(S[r], __fmul_rn(v, v));
        }
    g_xnorm[p] = reduce8_pattern(S);
}

// ---------------- kernel 4: HMMA GEMM screening + argmin ----------------
// CTA: 128 pixels x 1024 codes; 8 code tiles of 128; K'=768 in 12 chunks of 64.
// Warps: 4(M) x 2(N). Warp tile 32x64 -> acc[2][8][4].
// Smem rows padded to 72 halves (36 b32): STS.128 and frag LDS conflict-free.
__global__ __launch_bounds__(256)
void vq_gemm_kernel() {
    __shared__ __align__(16) __nv_bfloat16 As[128 * 72];
    __shared__ __align__(16) __nv_bfloat16 Bs[128 * 72];
    __shared__ float en_s[NUM_EMB];
    __shared__ float mb1[128];
    __shared__ float mb2[128];
    __shared__ int mi1s[128];

    const int tid = threadIdx.x;
    const int wid = tid >> 5;
    const int lane = tid & 31;
    const int wm = wid & 3;        // M slice: rows 32*wm .. +31
    const int wn = wid >> 2;       // N half: cols 64*wn within 128-code tile
    const int g = lane >> 2;
    const int t = lane & 3;

    const int pix0 = blockIdx.x * 128;

    for (int i = tid; i < NUM_EMB; i += 256) en_s[i] = g_enorm[i];

    // Per-lane pixel slots: s=0:(mi0,row g) s=1:(mi0,row g+8) s=2:(mi1,g) s=3:(mi1,g+8)
    float a_p[4];
    int rowOf[4];
#pragma unroll
    for (int s = 0; s < 4; s++) {
        rowOf[s] = 32 * wm + 16 * (s >> 1) + 8 * (s & 1) + g;
        a_p[s] = g_xnorm[pix0 + rowOf[s]];
    }

    float b1[4], b2[4];
    int i1[4];
#pragma unroll
    for (int s = 0; s < 4; s++) { b1[s] = 3.4e38f; b2[s] = 3.4e38f; i1[s] = 0; }

    const uint32_t* Xp32 = (const uint32_t*)g_Xp;   // row stride 384 b32
    const uint32_t* Ep32 = (const uint32_t*)g_Ep;
    const uint32_t* As32 = (const uint32_t*)As;
    const uint32_t* Bs32 = (const uint32_t*)Bs;

    for (int tile = 0; tile < 8; tile++) {
        const int n0 = tile * 128;
        float acc[2][8][4];
#pragma unroll
        for (int mi = 0; mi < 2; mi++)
#pragma unroll
            for (int ni = 0; ni < 8; ni++)
#pragma unroll
                for (int q = 0; q < 4; q++) acc[mi][ni][q] = 0.f;

        for (int kc = 0; kc < 12; kc++) {
            __syncthreads();
            // Fill A[128x64] and B[128x64] (16B per thread-iter, 4 iters each)
#pragma unroll
            for (int it = 0; it < 4; it++) {
                int id = tid + it * 256;
                int row = id >> 3, cj = id & 7;
                uint4 va = *(const uint4*)&Xp32[(size_t)(pix0 + row) * 384 + kc * 32 + cj * 4];
                *(uint4*)&As[row * 72 + cj * 8] = va;
                uint4 vb = *(const uint4*)&Ep32[(size_t)(n0 + row) * 384 + kc * 32 + cj * 4];
                *(uint4*)&Bs[row * 72 + cj * 8] = vb;
            }
            __syncthreads();
#pragma unroll
            for (int kf = 0; kf < 4; kf++) {
                uint32_t a[2][4];
#pragma unroll
                for (int mi = 0; mi < 2; mi++) {
                    int r0 = (32 * wm + 16 * mi + g) * 36 + 8 * kf + t;
                    a[mi][0] = As32[r0];
                    a[mi][1] = As32[r0 + 8 * 36];
                    a[mi][2] = As32[r0 + 4];
                    a[mi][3] = As32[r0 + 8 * 36 + 4];
                }
#pragma unroll
                for (int ni = 0; ni < 8; ni++) {
                    int nr = (64 * wn + 8 * ni + g) * 36 + 8 * kf + t;
                    uint32_t bb0 = Bs32[nr];
                    uint32_t bb1 = Bs32[nr + 4];
#pragma unroll
                    for (int mi = 0; mi < 2; mi++)
                        MMA16816(acc[mi][ni], a[mi][0], a[mi][1], a[mi][2], a[mi][3], bb0, bb1);
                }
            }
        }
        // Epilogue: reference-rounded scores.
        // c-frag layout: acc[.][.][0]=(g,2t) [1]=(g,2t+1) [2]=(g+8,2t) [3]=(g+8,2t+1)
        // -> slot s = 2*mi + (q>>1) pairs with acc element q (k ascending within slot).
#pragma unroll
        for (int ni = 0; ni < 8; ni++) {
            int kb = n0 + 64 * wn + 8 * ni + 2 * t;
            float c0 = en_s[kb], c1 = en_s[kb + 1];
#pragma unroll
            for (int mi = 0; mi < 2; mi++) {
#pragma unroll
                for (int q = 0; q < 4; q++) {
                    int s = 2 * mi + (q >> 1);
                    float bv = acc[mi][ni][q];
                    int k = kb + (q & 1);
                    float cn = (q & 1) ? c1 : c0;
                    float sc = __fadd_rn(__fsub_rn(a_p[s], __fmul_rn(2.0f, bv)), cn);
                    if (sc < b1[s]) { b2[s] = b1[s]; b1[s] = sc; i1[s] = k; }
                    else if (sc < b2[s]) { b2[s] = sc; }
                }
            }
        }
    }

    // Reduce across the 4 t-lanes of each g-group (lanes 4g..4g+3).
#pragma unroll
    for (int s = 0; s < 4; s++) {
        float x1 = b1[s], x2 = b2[s];
        int xi = i1[s];
#pragma unroll
        for (int off = 2; off > 0; off >>= 1) {
            float o1 = __shfl_down_sync(0xffffffffu, x1, off, 4);
            float o2 = __shfl_down_sync(0xffffffffu, x2, off, 4);
            int oi = __shfl_down_sync(0xffffffffu, xi, off, 4);
            float n2 = fminf(fmaxf(x1, o1), fminf(x2, o2));
            if (o1 < x1 || (o1 == x1 && oi < xi)) { x1 = o1; xi = oi; }
            x2 = n2;
        }
        b1[s] = x1; b2[s] = x2; i1[s] = xi;
    }
    if (wn == 0 && t == 0) {
#pragma unroll
        for (int s = 0; s < 4; s++) {
            mb1[rowOf[s]] = b1[s];
            mb2[rowOf[s]] = b2[s];
            mi1s[rowOf[s]] = i1[s];
        }
    }
    __syncthreads();
    if (wn == 1 && t == 0) {
#pragma unroll
        for (int s = 0; s < 4; s++) {
            int r = rowOf[s];
            float o1 = mb1[r], o2 = mb2[r];
            int oi = mi1s[r];
            float n2 = fminf(fmaxf(b1[s], o1), fminf(b2[s], o2));
            float n1;
            int ni_;
            if (o1 < b1[s] || (o1 == b1[s] && oi < i1[s])) { n1 = o1; ni_ = oi; }
            else { n1 = b1[s]; ni_ = i1[s]; }
            int p = pix0 + r;
            g_idx[p] = ni_;
            if (n2 - n1 < MARGIN) {
                int rr = atomicAdd(&g_resc_count, 1);
                g_resc[rr] = p;
            }
        }
    }
}

// ---------------- kernel 5: exact rescue for flagged pixels ----------------
__global__ __launch_bounds__(256)
void vq_rescue_kernel(const float* __restrict__ x, const float* __restrict__ emb) {
    __shared__ float xsm[EMB_DIM];
    __shared__ float rs[256];
    __shared__ int rk[256];
    const int tid = threadIdx.x;
    const int cnt = g_resc_count;

    for (int r = blockIdx.x; r < cnt; r += gridDim.x) {
        const int p = g_resc[r];
        const int b = p >> 12;
        const int hw = p & (HW - 1);
        __syncthreads();
        if (tid < EMB_DIM)
            xsm[tid] = x[((size_t)b * EMB_DIM + tid) * HW + hw];
        __syncthreads();
        const float a = g_xnorm[p];

        float ls = 3.4e38f;
        int lk = 0;
#pragma unroll
        for (int q = 0; q < 4; q++) {
            int k = tid + q * 256;           // ascending per thread
            const float* er = emb + (size_t)k * EMB_DIM;
            float bb = 0.f;
            for (int c = 0; c < EMB_DIM; c++)
                bb = fmaf(xsm[c], er[c], bb);
            float s = __fadd_rn(__fsub_rn(a, __fmul_rn(2.0f, bb)), g_enorm[k]);
            if (s < ls) { ls = s; lk = k; }
        }
        rs[tid] = ls; rk[tid] = lk;
        __syncthreads();
        for (int off = 128; off > 0; off >>= 1) {
            if (tid < off) {
                float so = rs[tid + off];
                int ko = rk[tid + off];
                if (so < rs[tid] || (so == rs[tid] && ko < rk[tid])) {
                    rs[tid] = so; rk[tid] = ko;
                }
            }
            __syncthreads();
        }
        if (tid == 0) g_idx[p] = rk[0];
    }
}

// ---------------- kernel 6: gather/writeback + loss ----------------
__global__ __launch_bounds__(256)
void vq_writeback_kernel(const float* __restrict__ x,
                         const float* __restrict__ emb,
                         float* __restrict__ out) {
    __shared__ int sidx[128];
    __shared__ double s_loss[8];
    const int tid = threadIdx.x;
    const int pix0 = blockIdx.x * 128;
    const int b = pix0 >> 12;
    const int hw0 = pix0 & (HW - 1);
    const float* xbase = x + ((size_t)b * EMB_DIM) * HW + hw0;

    if (tid < 128) sidx[tid] = g_idx[pix0 + tid];
    __syncthreads();

    float lsum = 0.f;
#pragma unroll 4
    for (int it = 0; it < (128 * EMB_DIM) / 256; it++) {
        int i = tid + it * 256;
        int p = i & 127;
        int c = i >> 7;
        int idx = sidx[p];
        float q = __ldg(&emb[(size_t)idx * EMB_DIM + c]);
        float xv = xbase[(size_t)c * HW + p];
        out[1 + ((size_t)b * EMB_DIM + c) * HW + hw0 + p] = q;
        float d = q - xv;
        lsum = fmaf(d, d, lsum);
    }
#pragma unroll
    for (int off = 16; off > 0; off >>= 1)
        lsum += __shfl_down_sync(0xffffffffu, lsum, off);
    if ((tid & 31) == 0) s_loss[tid >> 5] = (double)lsum;
    __syncthreads();
    if (tid == 0) {
        double tt = 0.0;
#pragma unroll
        for (int w = 0; w < 8; w++) tt += s_loss[w];
        atomicAdd(&g_loss, tt);
    }
}

__global__ void vq_finalize_kernel(float* __restrict__ out) {
    out[0] = (float)(g_loss * (1.0625 / 16777216.0));
}

extern "C" void kernel_launch(void* const* d_in, const int* in_sizes, int n_in,
                              void* d_out, int out_size) {
    const float* x = (const float*)d_in[0];
    const float* emb = (const float*)d_in[1];
    float* out = (float*)d_out;

    vq_init_kernel<<<4, 256>>>(emb);
    vq_xsplit_kernel<<<NPIX / 128, 256>>>(x);
    vq_xnorm_kernel<<<NPIX / 256, 256>>>(x);
    vq_gemm_kernel<<<NPIX / 128, 256>>>();
    vq_rescue_kernel<<<256, 256>>>(x, emb);
    vq_writeback_kernel<<<NPIX / 128, 256>>>(x, emb, out);
    vq_finalize_kernel<<<1, 1>>>(out);
}

// round 11
// speedup vs baseline: 1.1327x; 1.1327x over previous
#include <cuda_runtime.h>
#include <cuda_bf16.h>
#include <cstdint>

// VQ-VAE quantizer: bf16-split HMMA screening (cp.async double-buffered) +
// exact-chain rescue, reproducing the JAX/XLA-CPU fp32 reference argmin.
//   x: [16, 256, 64, 64] f32   (d_in[0])
//   emb: [1024, 256] f32       (d_in[1])
//   out: [1 + 16*256*64*64] f32: out[0]=c_loss, out[1:]=quant_out (NCHW)

#define NUM_EMB 1024
#define EMB_DIM 256
#define HW 4096
#define NPIX 65536
#define KSPLIT 768              // [hi | hi | lo] x [hi | lo | hi]
#define MARGIN 1.5e-4f
#define STAGE_B 18432           // 128 rows x 72 halves x 2B
#define GEMM_DSMEM (4 * STAGE_B)

__device__ double g_loss;
__device__ float g_enorm[NUM_EMB];
__device__ float g_xnorm[NPIX];
__device__ int g_idx[NPIX];
__device__ int g_resc_count;
__device__ int g_resc[NPIX];
__device__ __nv_bfloat16 g_Xp[(size_t)NPIX * KSPLIT];   // [pixel][768]
__device__ __nv_bfloat16 g_Ep[NUM_EMB * KSPLIT];        // [code][768]

#define MMA16816(d, a0, a1, a2, a3, bb0, bb1) \
    asm volatile("mma.sync.aligned.m16n8k16.row.col.f32.bf16.bf16.f32 " \
                 "{%0,%1,%2,%3}, {%4,%5,%6,%7}, {%8,%9}, {%0,%1,%2,%3};" \
                 : "+f"((d)[0]), "+f"((d)[1]), "+f"((d)[2]), "+f"((d)[3]) \
                 : "r"(a0), "r"(a1), "r"(a2), "r"(a3), "r"(bb0), "r"(bb1))
#define CPASYNC16(dst_u32, src) \
    asm volatile("cp.async.cg.shared.global [%0], [%1], 16;" \
                 :: "r"(dst_u32), "l"(src) : "memory")
#define CPCOMMIT() asm volatile("cp.async.commit_group;" ::: "memory")
#define CPWAIT1() asm volatile("cp.async.wait_group 1;" ::: "memory")
#define CPWAIT0() asm volatile("cp.async.wait_group 0;" ::: "memory")

__device__ __forceinline__ uint32_t smem_u32(const void* p) {
    uint32_t a;
    asm("{ .reg .u64 t; cvta.to.shared.u64 t, %1; cvt.u32.u64 %0, t; }" : "=r"(a) : "l"(p));
    return a;
}

// ---------------- reference-rounding helper ----------------
__device__ __forceinline__ float reduce8_pattern(const float S[8]) {
    float t02 = __fadd_rn(__fadd_rn(S[0], S[4]), __fadd_rn(S[2], S[6]));
    float t13 = __fadd_rn(__fadd_rn(S[1], S[5]), __fadd_rn(S[3], S[7]));
    return __fadd_rn(t02, t13);
}

// ---------------- kernel 1a: coalesced E split (+ zero accumulators) --------
__global__ void vq_esplit_kernel(const float* __restrict__ emb) {
    const int k = blockIdx.x;       // 1024 blocks
    const int c = threadIdx.x;      // 256 threads
    if (k == 0 && c == 0) { g_loss = 0.0; g_resc_count = 0; }
    float v = emb[(size_t)k * EMB_DIM + c];
    __nv_bfloat16 hi = __float2bfloat16_rn(v);
    __nv_bfloat16 lo = __float2bfloat16_rn(v - __bfloat162float(hi));
    __nv_bfloat16* er = g_Ep + (size_t)k * KSPLIT;
    er[c] = hi; er[256 + c] = lo; er[512 + c] = hi;
}

// ---------------- kernel 1b: ||e_k||^2, 8 lanes/code, exact XLA tree --------
__global__ void vq_enorm_kernel(const float* __restrict__ emb) {
    const int tid = threadIdx.x;
    const int gw = (blockIdx.x * blockDim.x + tid) >> 5;  // global warp 0..255
    const int lane = tid & 31;
    const int k = gw * 4 + (lane >> 3);
    const int r = lane & 7;
    const float* row = emb + (size_t)k * EMB_DIM;
    float S = 0.f;
#pragma unroll 8
    for (int j = 0; j < 32; j++) {
        float v = row[r + 8 * j];
        S = __fadd_rn(S, __fmul_rn(v, v));
    }
    // tree: T_r=S_r+S_{r+4}; U_r=T_r+T_{r+2}; R=U0+U1  == reduce8_pattern
    float o = __shfl_down_sync(0xffffffffu, S, 4, 8);
    float T = __fadd_rn(S, o);
    o = __shfl_down_sync(0xffffffffu, T, 2, 8);
    float U = __fadd_rn(T, o);
    o = __shfl_down_sync(0xffffffffu, U, 1, 8);
    float R = __fadd_rn(U, o);
    if (r == 0) g_enorm[k] = R;
}

// ---------------- kernel 2: split X into [hi | hi | lo] row-major ----------
__global__ __launch_bounds__(256)
void vq_xsplit_kernel(const float* __restrict__ x) {
    __shared__ float xs[128 * 66];   // [p][c], stride 66
    const int tid = threadIdx.x;
    const int pix0 = blockIdx.x * 128;
    const int b = pix0 >> 12;
    const int hw0 = pix0 & (HW - 1);
    const float* xbase = x + ((size_t)b * EMB_DIM) * HW + hw0;

    for (int c0 = 0; c0 < EMB_DIM; c0 += 64) {
        __syncthreads();
#pragma unroll
        for (int it = 0; it < 32; it++) {
            int i = tid + it * 256;
            int p = i & 127, c = i >> 7;
            xs[p * 66 + c] = xbase[(size_t)(c0 + c) * HW + p];
        }
        __syncthreads();
#pragma unroll
        for (int it = 0; it < 16; it++) {
            int i = tid + it * 256;
            int p = i >> 5, cp = i & 31;
            float2 v = *(const float2*)&xs[p * 66 + 2 * cp];
            __nv_bfloat16 h0 = __float2bfloat16_rn(v.x);
            __nv_bfloat16 l0 = __float2bfloat16_rn(v.x - __bfloat162float(h0));
            __nv_bfloat16 h1 = __float2bfloat16_rn(v.y);
            __nv_bfloat16 l1 = __float2bfloat16_rn(v.y - __bfloat162float(h1));
            size_t row = (size_t)(pix0 + p) * KSPLIT;
            __nv_bfloat162 hh; hh.x = h0; hh.y = h1;
            __nv_bfloat162 ll; ll.x = l0; ll.y = l1;
            *(__nv_bfloat162*)&g_Xp[row + c0 + 2 * cp] = hh;
            *(__nv_bfloat162*)&g_Xp[row + 256 + c0 + 2 * cp] = hh;
            *(__nv_bfloat162*)&g_Xp[row + 512 + c0 + 2 * cp] = ll;
        }
    }
}

// ---------------- kernel 3: per-pixel ||x||^2 with reference pattern -------
__global__ __launch_bounds__(256)
void vq_xnorm_kernel(const float* __restrict__ x) {
    int p = blockIdx.x * 256 + threadIdx.x;
    int b = p >> 12;
    int hw = p & (HW - 1);
    const float* xb = x + ((size_t)b * EMB_DIM) * HW + hw;
    float S[8];
#pragma unroll
    for (int r = 0; r < 8; r++) S[r] = 0.f;
    for (int c = 0; c < EMB_DIM; c += 8)
#pragma unroll
        for (int r = 0; r < 8; r++) {
            float v = xb[(size_t)(c + r) * HW];
            S[r] = __fadd_rn(S[r], __fmul_rn(v, v));
        }
    g_xnorm[p] = reduce8_pattern(S);
}

// ---------------- kernel 4: HMMA GEMM screening + argmin (cp.async x2) -----
// CTA: 128 pixels x 1024 codes; 8 code tiles of 128; K'=768 in 12 chunks of 64.
// Warps: 4(M) x 2(N). Warp tile 32x64 -> acc[2][8][4]. Smem rows 72 halves.
__global__ __launch_bounds__(256, 2)
void vq_gemm_kernel() {
    extern __shared__ __align__(16) char dsm[];
    __nv_bfloat16* As = (__nv_bfloat16*)dsm;                    // 2 stages
    __nv_bfloat16* Bs = (__nv_bfloat16*)(dsm + 2 * STAGE_B);    // 2 stages
    __shared__ float mb1[128];
    __shared__ float mb2[128];
    __shared__ int mi1s[128];

    const int tid = threadIdx.x;
    const int lane = tid & 31;
    const int wid = tid >> 5;
    const int wm = wid & 3;
    const int wn = wid >> 2;
    const int g = lane >> 2;
    const int t = lane & 3;
    const int pix0 = blockIdx.x * 128;

    const uint32_t sA = smem_u32(As);
    const uint32_t sB = smem_u32(Bs);
    const char* XpB = (const char*)g_Xp;
    const char* EpB = (const char*)g_Ep;
    const uint32_t* As32 = (const uint32_t*)As;
    const uint32_t* Bs32 = (const uint32_t*)Bs;

    // fill coords (4 iterations of 256 threads -> 128 rows x 8 16B-chunks)
    int frow[4], fcj[4];
#pragma unroll
    for (int it = 0; it < 4; it++) {
        int id = tid + it * 256;
        frow[it] = id >> 3;
        fcj[it] = id & 7;
    }

    float a_p[4];
    int rowOf[4];
#pragma unroll
    for (int s = 0; s < 4; s++) {
        rowOf[s] = 32 * wm + 16 * (s >> 1) + 8 * (s & 1) + g;
        a_p[s] = g_xnorm[pix0 + rowOf[s]];
    }
    float b1[4], b2[4];
    int i1[4];
#pragma unroll
    for (int s = 0; s < 4; s++) { b1[s] = 3.4e38f; b2[s] = 3.4e38f; i1[s] = 0; }

    for (int tile = 0; tile < 8; tile++) {
        const int n0 = tile * 128;
        float acc[2][8][4];
#pragma unroll
        for (int mi = 0; mi < 2; mi++)
#pragma unroll
            for (int ni = 0; ni < 8; ni++)
#pragma unroll
                for (int q = 0; q < 4; q++) acc[mi][ni][q] = 0.f;

        // prefetch chunk 0 into stage 0
#pragma unroll
        for (int it = 0; it < 4; it++) {
            uint32_t doff = (uint32_t)(frow[it] * 144 + fcj[it] * 16);
            CPASYNC16(sA + doff, XpB + ((size_t)(pix0 + frow[it]) * 768 + fcj[it] * 8) * 2);
            CPASYNC16(sB + doff, EpB + ((size_t)(n0 + frow[it]) * 768 + fcj[it] * 8) * 2);
        }
        CPCOMMIT();

        for (int kc = 0; kc < 12; kc++) {
            const int st = kc & 1;
            if (kc + 1 < 12) {
                const int st2 = st ^ 1;
#pragma unroll
                for (int it = 0; it < 4; it++) {
                    uint32_t doff = (uint32_t)(st2 * STAGE_B + frow[it] * 144 + fcj[it] * 16);
                    size_t koff = (size_t)(kc + 1) * 64 + fcj[it] * 8;
                    CPASYNC16(sA + doff, XpB + ((size_t)(pix0 + frow[it]) * 768 + koff) * 2);
                    CPASYNC16(sB + doff, EpB + ((size_t)(n0 + frow[it]) * 768 + koff) * 2);
                }
                CPCOMMIT();
                CPWAIT1();
            } else {
                CPWAIT0();
            }
            __syncthreads();

            const int so = st * 4608;   // stage offset in b32 units
#pragma unroll
            for (int kf = 0; kf < 4; kf++) {
                uint32_t a[2][4];
#pragma unroll
                for (int mi = 0; mi < 2; mi++) {
                    int r0 = so + (32 * wm + 16 * mi + g) * 36 + 8 * kf + t;
                    a[mi][0] = As32[r0];
                    a[mi][1] = As32[r0 + 8 * 36];
                    a[mi][2] = As32[r0 + 4];
                    a[mi][3] = As32[r0 + 8 * 36 + 4];
                }
#pragma unroll
                for (int ni = 0; ni < 8; ni++) {
                    int nr = so + (64 * wn + 8 * ni + g) * 36 + 8 * kf + t;
                    uint32_t bb0 = Bs32[nr];
                    uint32_t bb1 = Bs32[nr + 4];
#pragma unroll
                    for (int mi = 0; mi < 2; mi++)
                        MMA16816(acc[mi][ni], a[mi][0], a[mi][1], a[mi][2], a[mi][3], bb0, bb1);
                }
            }
            __syncthreads();
        }

        // Epilogue: reference-rounded scores.
        // c-frag: q0=(g,2t) q1=(g,2t+1) q2=(g+8,2t) q3=(g+8,2t+1); slot s=2mi+(q>>1).
#pragma unroll
        for (int ni = 0; ni < 8; ni++) {
            int kb = n0 + 64 * wn + 8 * ni + 2 * t;
            float c0 = __ldg(&g_enorm[kb]);
            float c1 = __ldg(&g_enorm[kb + 1]);
#pragma unroll
            for (int mi = 0; mi < 2; mi++) {
#pragma unroll
                for (int q = 0; q < 4; q++) {
                    int s = 2 * mi + (q >> 1);
                    float bv = acc[mi][ni][q];
                    int k = kb + (q & 1);
                    float cn = (q & 1) ? c1 : c0;
                    float sc = __fadd_rn(__fsub_rn(a_p[s], __fmul_rn(2.0f, bv)), cn);
                    if (sc < b1[s]) { b2[s] = b1[s]; b1[s] = sc; i1[s] = k; }
                    else if (sc < b2[s]) { b2[s] = sc; }
                }
            }
        }
    }

    // Reduce across the 4 t-lanes of each g-group.
#pragma unroll
    for (int s = 0; s < 4; s++) {
        float x1 = b1[s], x2 = b2[s];
        int xi = i1[s];
#pragma unroll
        for (int off = 2; off > 0; off >>= 1) {
            float o1 = __shfl_down_sync(0xffffffffu, x1, off, 4);
            float o2 = __shfl_down_sync(0xffffffffu, x2, off, 4);
            int oi = __shfl_down_sync(0xffffffffu, xi, off, 4);
            float n2 = fminf(fmaxf(x1, o1), fminf(x2, o2));
            if (o1 < x1 || (o1 == x1 && oi < xi)) { x1 = o1; xi = oi; }
            x2 = n2;
        }
        b1[s] = x1; b2[s] = x2; i1[s] = xi;
    }
    if (wn == 0 && t == 0) {
#pragma unroll
        for (int s = 0; s < 4; s++) {
            mb1[rowOf[s]] = b1[s];
            mb2[rowOf[s]] = b2[s];
            mi1s[rowOf[s]] = i1[s];
        }
    }
    __syncthreads();
    if (wn == 1 && t == 0) {
#pragma unroll
        for (int s = 0; s < 4; s++) {
            int r = rowOf[s];
            float o1 = mb1[r], o2 = mb2[r];
            int oi = mi1s[r];
            float n2 = fminf(fmaxf(b1[s], o1), fminf(b2[s], o2));
            float n1;
            int ni_;
            if (o1 < b1[s] || (o1 == b1[s] && oi < i1[s])) { n1 = o1; ni_ = oi; }
            else { n1 = b1[s]; ni_ = i1[s]; }
            int p = pix0 + r;
            g_idx[p] = ni_;
            if (n2 - n1 < MARGIN) {
                int rr = atomicAdd(&g_resc_count, 1);
                g_resc[rr] = p;
            }
        }
    }
}

// ---------------- kernel 5: exact rescue for flagged pixels ----------------
__global__ __launch_bounds__(256)
void vq_rescue_kernel(const float* __restrict__ x, const float* __restrict__ emb) {
    __shared__ float xsm[EMB_DIM];
    __shared__ float rs[256];
    __shared__ int rk[256];
    const int tid = threadIdx.x;
    const int cnt = g_resc_count;

    for (int r = blockIdx.x; r < cnt; r += gridDim.x) {
        const int p = g_resc[r];
        const int b = p >> 12;
        const int hw = p & (HW - 1);
        __syncthreads();
        if (tid < EMB_DIM)
            xsm[tid] = x[((size_t)b * EMB_DIM + tid) * HW + hw];
        __syncthreads();
        const float a = g_xnorm[p];

        float ls = 3.4e38f;
        int lk = 0;
#pragma unroll
        for (int q = 0; q < 4; q++) {
            int k = tid + q * 256;           // ascending per thread
            const float* er = emb + (size_t)k * EMB_DIM;
            float bb = 0.f;
            for (int c = 0; c < EMB_DIM; c++)
                bb = fmaf(xsm[c], er[c], bb);
            float s = __fadd_rn(__fsub_rn(a, __fmul_rn(2.0f, bb)), g_enorm[k]);
            if (s < ls) { ls = s; lk = k; }
        }
        rs[tid] = ls; rk[tid] = lk;
        __syncthreads();
        for (int off = 128; off > 0; off >>= 1) {
            if (tid < off) {
                float so = rs[tid + off];
                int ko = rk[tid + off];
                if (so < rs[tid] || (so == rs[tid] && ko < rk[tid])) {
                    rs[tid] = so; rk[tid] = ko;
                }
            }
            __syncthreads();
        }
        if (tid == 0) g_idx[p] = rk[0];
    }
}

// ---------------- kernel 6: gather/writeback + loss ----------------
__global__ __launch_bounds__(256)
void vq_writeback_kernel(const float* __restrict__ x,
                         const float* __restrict__ emb,
                         float* __restrict__ out) {
    __shared__ int sidx[128];
    __shared__ double s_loss[8];
    const int tid = threadIdx.x;
    const int pix0 = blockIdx.x * 128;
    const int b = pix0 >> 12;
    const int hw0 = pix0 & (HW - 1);
    const float* xbase = x + ((size_t)b * EMB_DIM) * HW + hw0;

    if (tid < 128) sidx[tid] = g_idx[pix0 + tid];
    __syncthreads();

    float lsum = 0.f;
#pragma unroll 4
    for (int it = 0; it < (128 * EMB_DIM) / 256; it++) {
        int i = tid + it * 256;
        int p = i & 127;
        int c = i >> 7;
        int idx = sidx[p];
        float q = __ldg(&emb[(size_t)idx * EMB_DIM + c]);
        float xv = xbase[(size_t)c * HW + p];
        out[1 + ((size_t)b * EMB_DIM + c) * HW + hw0 + p] = q;
        float d = q - xv;
        lsum = fmaf(d, d, lsum);
    }
#pragma unroll
    for (int off = 16; off > 0; off >>= 1)
        lsum += __shfl_down_sync(0xffffffffu, lsum, off);
    if ((tid & 31) == 0) s_loss[tid >> 5] = (double)lsum;
    __syncthreads();
    if (tid == 0) {
        double tt = 0.0;
#pragma unroll
        for (int w = 0; w < 8; w++) tt += s_loss[w];
        atomicAdd(&g_loss, tt);
    }
}

__global__ void vq_finalize_kernel(float* __restrict__ out) {
    out[0] = (float)(g_loss * (1.0625 / 16777216.0));
}

extern "C" void kernel_launch(void* const* d_in, const int* in_sizes, int n_in,
                              void* d_out, int out_size) {
    const float* x = (const float*)d_in[0];
    const float* emb = (const float*)d_in[1];
    float* out = (float*)d_out;

    cudaFuncSetAttribute(vq_gemm_kernel,
                         cudaFuncAttributeMaxDynamicSharedMemorySize, GEMM_DSMEM);

    vq_esplit_kernel<<<NUM_EMB, 256>>>(emb);
    vq_enorm_kernel<<<NUM_EMB / 32, 256>>>(emb);
    vq_xsplit_kernel<<<NPIX / 128, 256>>>(x);
    vq_xnorm_kernel<<<NPIX / 256, 256>>>(x);
    vq_gemm_kernel<<<NPIX / 128, 256, GEMM_DSMEM>>>();
    vq_rescue_kernel<<<256, 256>>>(x, emb);
    vq_writeback_kernel<<<NPIX / 128, 256>>>(x, emb, out);
    vq_finalize_kernel<<<1, 1>>>(out);
}

// round 12
// speedup vs baseline: 3.8526x; 3.4014x over previous
#include <cuda_runtime.h>
#include <cuda_bf16.h>
#include <cstdint>

// VQ-VAE quantizer: bf16-split HMMA screening (cp.async double-buffered) +
// exact-chain rescue (coalesced, 16 pixels/block), reproducing the
// JAX/XLA-CPU fp32 reference argmin bitwise.
//   x: [16, 256, 64, 64] f32   (d_in[0])
//   emb: [1024, 256] f32       (d_in[1])
//   out: [1 + 16*256*64*64] f32: out[0]=c_loss, out[1:]=quant_out (NCHW)

#define NUM_EMB 1024
#define EMB_DIM 256
#define HW 4096
#define NPIX 65536
#define KSPLIT 768              // [hi | hi | lo] x [hi | lo | hi]
#define MARGIN 1.5e-4f
#define STAGE_B 18432           // 128 rows x 72 halves x 2B
#define GEMM_DSMEM (4 * STAGE_B)
#define RESC_PIX 16

__device__ double g_loss;
__device__ float g_enorm[NUM_EMB];
__device__ float g_xnorm[NPIX];
__device__ int g_idx[NPIX];
__device__ int g_resc_count;
__device__ int g_resc[NPIX];
__device__ __nv_bfloat16 g_Xp[(size_t)NPIX * KSPLIT];   // [pixel][768]
__device__ __nv_bfloat16 g_Ep[NUM_EMB * KSPLIT];        // [code][768]
__device__ float g_EpT[EMB_DIM * NUM_EMB];              // [c][k] transposed emb

#define MMA16816(d, a0, a1, a2, a3, bb0, bb1) \
    asm volatile("mma.sync.aligned.m16n8k16.row.col.f32.bf16.bf16.f32 " \
                 "{%0,%1,%2,%3}, {%4,%5,%6,%7}, {%8,%9}, {%0,%1,%2,%3};" \
                 : "+f"((d)[0]), "+f"((d)[1]), "+f"((d)[2]), "+f"((d)[3]) \
                 : "r"(a0), "r"(a1), "r"(a2), "r"(a3), "r"(bb0), "r"(bb1))
#define CPASYNC16(dst_u32, src) \
    asm volatile("cp.async.cg.shared.global [%0], [%1], 16;" \
                 :: "r"(dst_u32), "l"(src) : "memory")
#define CPCOMMIT() asm volatile("cp.async.commit_group;" ::: "memory")
#define CPWAIT1() asm volatile("cp.async.wait_group 1;" ::: "memory")
#define CPWAIT0() asm volatile("cp.async.wait_group 0;" ::: "memory")

__device__ __forceinline__ uint32_t smem_u32(const void* p) {
    uint32_t a;
    asm("{ .reg .u64 t; cvta.to.shared.u64 t, %1; cvt.u32.u64 %0, t; }" : "=r"(a) : "l"(p));
    return a;
}

// ---------------- reference-rounding helper ----------------
__device__ __forceinline__ float reduce8_pattern(const float S[8]) {
    float t02 = __fadd_rn(__fadd_rn(S[0], S[4]), __fadd_rn(S[2], S[6]));
    float t13 = __fadd_rn(__fadd_rn(S[1], S[5]), __fadd_rn(S[3], S[7]));
    return __fadd_rn(t02, t13);
}

// ---------------- kernel 1a: coalesced E split (+ zero accumulators) --------
__global__ void vq_esplit_kernel(const float* __restrict__ emb) {
    const int k = blockIdx.x;       // 1024 blocks
    const int c = threadIdx.x;      // 256 threads
    if (k == 0 && c == 0) { g_loss = 0.0; g_resc_count = 0; }
    float v = emb[(size_t)k * EMB_DIM + c];
    __nv_bfloat16 hi = __float2bfloat16_rn(v);
    __nv_bfloat16 lo = __float2bfloat16_rn(v - __bfloat162float(hi));
    __nv_bfloat16* er = g_Ep + (size_t)k * KSPLIT;
    er[c] = hi; er[256 + c] = lo; er[512 + c] = hi;
}

// ---------------- kernel 1b: transpose emb -> g_EpT[c][k] -------------------
__global__ void vq_etrans_kernel(const float* __restrict__ emb) {
    const int c = blockIdx.x;       // 256 blocks
#pragma unroll
    for (int q = 0; q < 4; q++) {
        int k = threadIdx.x + q * 256;
        g_EpT[c * NUM_EMB + k] = emb[(size_t)k * EMB_DIM + c];
    }
}

// ---------------- kernel 1c: ||e_k||^2, 8 lanes/code, exact XLA tree --------
__global__ void vq_enorm_kernel(const float* __restrict__ emb) {
    const int tid = threadIdx.x;
    const int gw = (blockIdx.x * blockDim.x + tid) >> 5;  // global warp 0..255
    const int lane = tid & 31;
    const int k = gw * 4 + (lane >> 3);
    const int r = lane & 7;
    const float* row = emb + (size_t)k * EMB_DIM;
    float S = 0.f;
#pragma unroll 8
    for (int j = 0; j < 32; j++) {
        float v = row[r + 8 * j];
        S = __fadd_rn(S, __fmul_rn(v, v));
    }
    float o = __shfl_down_sync(0xffffffffu, S, 4, 8);
    float T = __fadd_rn(S, o);
    o = __shfl_down_sync(0xffffffffu, T, 2, 8);
    float U = __fadd_rn(T, o);
    o = __shfl_down_sync(0xffffffffu, U, 1, 8);
    float R = __fadd_rn(U, o);
    if (r == 0) g_enorm[k] = R;
}

// ---------------- kernel 2: split X into [hi | hi | lo] row-major ----------
__global__ __launch_bounds__(256)
void vq_xsplit_kernel(const float* __restrict__ x) {
    __shared__ float xs[128 * 66];   // [p][c], stride 66
    const int tid = threadIdx.x;
    const int pix0 = blockIdx.x * 128;
    const int b = pix0 >> 12;
    const int hw0 = pix0 & (HW - 1);
    const float* xbase = x + ((size_t)b * EMB_DIM) * HW + hw0;

    for (int c0 = 0; c0 < EMB_DIM; c0 += 64) {
        __syncthreads();
#pragma unroll
        for (int it = 0; it < 32; it++) {
            int i = tid + it * 256;
            int p = i & 127, c = i >> 7;
            xs[p * 66 + c] = xbase[(size_t)(c0 + c) * HW + p];
        }
        __syncthreads();
#pragma unroll
        for (int it = 0; it < 16; it++) {
            int i = tid + it * 256;
            int p = i >> 5, cp = i & 31;
            float2 v = *(const float2*)&xs[p * 66 + 2 * cp];
            __nv_bfloat16 h0 = __float2bfloat16_rn(v.x);
            __nv_bfloat16 l0 = __float2bfloat16_rn(v.x - __bfloat162float(h0));
            __nv_bfloat16 h1 = __float2bfloat16_rn(v.y);
            __nv_bfloat16 l1 = __float2bfloat16_rn(v.y - __bfloat162float(h1));
            size_t row = (size_t)(pix0 + p) * KSPLIT;
            __nv_bfloat162 hh; hh.x = h0; hh.y = h1;
            __nv_bfloat162 ll; ll.x = l0; ll.y = l1;
            *(__nv_bfloat162*)&g_Xp[row + c0 + 2 * cp] = hh;
            *(__nv_bfloat162*)&g_Xp[row + 256 + c0 + 2 * cp] = hh;
            *(__nv_bfloat162*)&g_Xp[row + 512 + c0 + 2 * cp] = ll;
        }
    }
}

// ---------------- kernel 3: per-pixel ||x||^2 with reference pattern -------
__global__ __launch_bounds__(256)
void vq_xnorm_kernel(const float* __restrict__ x) {
    int p = blockIdx.x * 256 + threadIdx.x;
    int b = p >> 12;
    int hw = p & (HW - 1);
    const float* xb = x + ((size_t)b * EMB_DIM) * HW + hw;
    float S[8];
#pragma unroll
    for (int r = 0; r < 8; r++) S[r] = 0.f;
    for (int c = 0; c < EMB_DIM; c += 8)
#pragma unroll
        for (int r = 0; r < 8; r++) {
            float v = xb[(size_t)(c + r) * HW];
            S[r] = __fadd_rn(S[r], __fmul_rn(v, v));
        }
    g_xnorm[p] = reduce8_pattern(S);
}

// ---------------- kernel 4: HMMA GEMM screening + argmin (cp.async x2) -----
__global__ __launch_bounds__(256, 2)
void vq_gemm_kernel() {
    extern __shared__ __align__(16) char dsm[];
    __nv_bfloat16* As = (__nv_bfloat16*)dsm;                    // 2 stages
    __nv_bfloat16* Bs = (__nv_bfloat16*)(dsm + 2 * STAGE_B);    // 2 stages
    __shared__ float mb1[128];
    __shared__ float mb2[128];
    __shared__ int mi1s[128];

    const int tid = threadIdx.x;
    const int lane = tid & 31;
    const int wid = tid >> 5;
    const int wm = wid & 3;
    const int wn = wid >> 2;
    const int g = lane >> 2;
    const int t = lane & 3;
    const int pix0 = blockIdx.x * 128;

    const uint32_t sA = smem_u32(As);
    const uint32_t sB = smem_u32(Bs);
    const char* XpB = (const char*)g_Xp;
    const char* EpB = (const char*)g_Ep;
    const uint32_t* As32 = (const uint32_t*)As;
    const uint32_t* Bs32 = (const uint32_t*)Bs;

    int frow[4], fcj[4];
#pragma unroll
    for (int it = 0; it < 4; it++) {
        int id = tid + it * 256;
        frow[it] = id >> 3;
        fcj[it] = id & 7;
    }

    float a_p[4];
    int rowOf[4];
#pragma unroll
    for (int s = 0; s < 4; s++) {
        rowOf[s] = 32 * wm + 16 * (s >> 1) + 8 * (s & 1) + g;
        a_p[s] = g_xnorm[pix0 + rowOf[s]];
    }
    float b1[4], b2[4];
    int i1[4];
#pragma unroll
    for (int s = 0; s < 4; s++) { b1[s] = 3.4e38f; b2[s] = 3.4e38f; i1[s] = 0; }

    for (int tile = 0; tile < 8; tile++) {
        const int n0 = tile * 128;
        float acc[2][8][4];
#pragma unroll
        for (int mi = 0; mi < 2; mi++)
#pragma unroll
            for (int ni = 0; ni < 8; ni++)
#pragma unroll
                for (int q = 0; q < 4; q++) acc[mi][ni][q] = 0.f;

#pragma unroll
        for (int it = 0; it < 4; it++) {
            uint32_t doff = (uint32_t)(frow[it] * 144 + fcj[it] * 16);
            CPASYNC16(sA + doff, XpB + ((size_t)(pix0 + frow[it]) * 768 + fcj[it] * 8) * 2);
            CPASYNC16(sB + doff, EpB + ((size_t)(n0 + frow[it]) * 768 + fcj[it] * 8) * 2);
        }
        CPCOMMIT();

        for (int kc = 0; kc < 12; kc++) {
            const int st = kc & 1;
            if (kc + 1 < 12) {
                const int st2 = st ^ 1;
#pragma unroll
                for (int it = 0; it < 4; it++) {
                    uint32_t doff = (uint32_t)(st2 * STAGE_B + frow[it] * 144 + fcj[it] * 16);
                    size_t koff = (size_t)(kc + 1) * 64 + fcj[it] * 8;
                    CPASYNC16(sA + doff, XpB + ((size_t)(pix0 + frow[it]) * 768 + koff) * 2);
                    CPASYNC16(sB + doff, EpB + ((size_t)(n0 + frow[it]) * 768 + koff) * 2);
                }
                CPCOMMIT();
                CPWAIT1();
            } else {
                CPWAIT0();
            }
            __syncthreads();

            const int so = st * 4608;
#pragma unroll
            for (int kf = 0; kf < 4; kf++) {
                uint32_t a[2][4];
#pragma unroll
                for (int mi = 0; mi < 2; mi++) {
                    int r0 = so + (32 * wm + 16 * mi + g) * 36 + 8 * kf + t;
                    a[mi][0] = As32[r0];
                    a[mi][1] = As32[r0 + 8 * 36];
                    a[mi][2] = As32[r0 + 4];
                    a[mi][3] = As32[r0 + 8 * 36 + 4];
                }
#pragma unroll
                for (int ni = 0; ni < 8; ni++) {
                    int nr = so + (64 * wn + 8 * ni + g) * 36 + 8 * kf + t;
                    uint32_t bb0 = Bs32[nr];
                    uint32_t bb1 = Bs32[nr + 4];
#pragma unroll
                    for (int mi = 0; mi < 2; mi++)
                        MMA16816(acc[mi][ni], a[mi][0], a[mi][1], a[mi][2], a[mi][3], bb0, bb1);
                }
            }
            __syncthreads();
        }

        // Epilogue: reference-rounded scores.
        // c-frag: q0=(g,2t) q1=(g,2t+1) q2=(g+8,2t) q3=(g+8,2t+1); slot s=2mi+(q>>1).
#pragma unroll
        for (int ni = 0; ni < 8; ni++) {
            int kb = n0 + 64 * wn + 8 * ni + 2 * t;
            float c0 = __ldg(&g_enorm[kb]);
            float c1 = __ldg(&g_enorm[kb + 1]);
#pragma unroll
            for (int mi = 0; mi < 2; mi++) {
#pragma unroll
                for (int q = 0; q < 4; q++) {
                    int s = 2 * mi + (q >> 1);
                    float bv = acc[mi][ni][q];
                    int k = kb + (q & 1);
                    float cn = (q & 1) ? c1 : c0;
                    float sc = __fadd_rn(__fsub_rn(a_p[s], __fmul_rn(2.0f, bv)), cn);
                    if (sc < b1[s]) { b2[s] = b1[s]; b1[s] = sc; i1[s] = k; }
                    else if (sc < b2[s]) { b2[s] = sc; }
                }
            }
        }
    }

#pragma unroll
    for (int s = 0; s < 4; s++) {
        float x1 = b1[s], x2 = b2[s];
        int xi = i1[s];
#pragma unroll
        for (int off = 2; off > 0; off >>= 1) {
            float o1 = __shfl_down_sync(0xffffffffu, x1, off, 4);
            float o2 = __shfl_down_sync(0xffffffffu, x2, off, 4);
            int oi = __shfl_down_sync(0xffffffffu, xi, off, 4);
            float n2 = fminf(fmaxf(x1, o1), fminf(x2, o2));
            if (o1 < x1 || (o1 == x1 && oi < xi)) { x1 = o1; xi = oi; }
            x2 = n2;
        }
        b1[s] = x1; b2[s] = x2; i1[s] = xi;
    }
    if (wn == 0 && t == 0) {
#pragma unroll
        for (int s = 0; s < 4; s++) {
            mb1[rowOf[s]] = b1[s];
            mb2[rowOf[s]] = b2[s];
            mi1s[rowOf[s]] = i1[s];
        }
    }
    __syncthreads();
    if (wn == 1 && t == 0) {
#pragma unroll
        for (int s = 0; s < 4; s++) {
            int r = rowOf[s];
            float o1 = mb1[r], o2 = mb2[r];
            int oi = mi1s[r];
            float n2 = fminf(fmaxf(b1[s], o1), fminf(b2[s], o2));
            float n1;
            int ni_;
            if (o1 < b1[s] || (o1 == b1[s] && oi < i1[s])) { n1 = o1; ni_ = oi; }
            else { n1 = b1[s]; ni_ = i1[s]; }
            int p = pix0 + r;
            g_idx[p] = ni_;
            if (n2 - n1 < MARGIN) {
                int rr = atomicAdd(&g_resc_count, 1);
                g_resc[rr] = p;
            }
        }
    }
}

// ---------------- kernel 5: exact rescue, 16 pixels/block, coalesced -------
// Per-(pixel,code) fp32 chain: strictly sequential over ascending c (Eigen
// order), identical final rounding ops -> bitwise reference scores.
__global__ __launch_bounds__(256)
void vq_rescue_kernel(const float* __restrict__ x) {
    __shared__ float xsm[RESC_PIX * 256];
    __shared__ int plist[RESC_PIX];
    __shared__ float rbs[RESC_PIX * 8];
    __shared__ int rbk[RESC_PIX * 8];
    const int tid = threadIdx.x;
    const int lane = tid & 31, wid = tid >> 5;
    const int cnt = g_resc_count;

    for (int base = blockIdx.x * RESC_PIX; base < cnt; base += gridDim.x * RESC_PIX) {
        const int nv = min(RESC_PIX, cnt - base);
        __syncthreads();
        if (tid < RESC_PIX)
            plist[tid] = g_resc[base + ((tid < nv) ? tid : 0)];
        __syncthreads();
        // stage the 16 x-rows (exact fp32)
        for (int j = wid; j < RESC_PIX; j += 8) {
            int p = plist[j];
            int b = p >> 12, hw = p & (HW - 1);
            const float* xb = x + ((size_t)b * EMB_DIM) * HW + hw;
            for (int c = lane; c < EMB_DIM; c += 32)
                xsm[j * 256 + c] = xb[(size_t)c * HW];
        }
        __syncthreads();

        float best[RESC_PIX];
        int bidx[RESC_PIX];
#pragma unroll
        for (int j = 0; j < RESC_PIX; j++) { best[j] = 3.4e38f; bidx[j] = 0; }

#pragma unroll
        for (int pass = 0; pass < 2; pass++) {
            const int k0 = tid + (2 * pass) * 256;      // ascending within thread
            const int k1 = tid + (2 * pass + 1) * 256;
            float acc0[RESC_PIX], acc1[RESC_PIX];
#pragma unroll
            for (int j = 0; j < RESC_PIX; j++) { acc0[j] = 0.f; acc1[j] = 0.f; }
            for (int c = 0; c < EMB_DIM; c++) {
                float e0 = g_EpT[c * NUM_EMB + k0];     // coalesced, L2-resident
                float e1 = g_EpT[c * NUM_EMB + k1];
#pragma unroll
                for (int j = 0; j < RESC_PIX; j++) {
                    float xv = xsm[j * 256 + c];        // broadcast LDS
                    acc0[j] = fmaf(xv, e0, acc0[j]);
                    acc1[j] = fmaf(xv, e1, acc1[j]);
                }
            }
            float en0 = g_enorm[k0], en1 = g_enorm[k1];
#pragma unroll
            for (int j = 0; j < RESC_PIX; j++) {
                float a = g_xnorm[plist[j]];
                float s0 = __fadd_rn(__fsub_rn(a, __fmul_rn(2.0f, acc0[j])), en0);
                float s1 = __fadd_rn(__fsub_rn(a, __fmul_rn(2.0f, acc1[j])), en1);
                if (s0 < best[j]) { best[j] = s0; bidx[j] = k0; }
                if (s1 < best[j]) { best[j] = s1; bidx[j] = k1; }
            }
        }
        // lexicographic (score, k) min == first-index rule (k distinct)
#pragma unroll
        for (int j = 0; j < RESC_PIX; j++) {
            float s = best[j];
            int k = bidx[j];
#pragma unroll
            for (int off = 16; off > 0; off >>= 1) {
                float so = __shfl_down_sync(0xffffffffu, s, off);
                int ko = __shfl_down_sync(0xffffffffu, k, off);
                if (so < s || (so == s && ko < k)) { s = so; k = ko; }
            }
            if (lane == 0) { rbs[j * 8 + wid] = s; rbk[j * 8 + wid] = k; }
        }
        __syncthreads();
        if (tid < nv) {
            float s = rbs[tid * 8];
            int k = rbk[tid * 8];
#pragma unroll
            for (int w = 1; w < 8; w++) {
                float so = rbs[tid * 8 + w];
                int ko = rbk[tid * 8 + w];
                if (so < s || (so == s && ko < k)) { s = so; k = ko; }
            }
            g_idx[plist[tid]] = k;
        }
    }
}

// ---------------- kernel 6: gather/writeback + loss ----------------
__global__ __launch_bounds__(256)
void vq_writeback_kernel(const float* __restrict__ x,
                         const float* __restrict__ emb,
                         float* __restrict__ out) {
    __shared__ int sidx[128];
    __shared__ double s_loss[8];
    const int tid = threadIdx.x;
    const int pix0 = blockIdx.x * 128;
    const int b = pix0 >> 12;
    const int hw0 = pix0 & (HW - 1);
    const float* xbase = x + ((size_t)b * EMB_DIM) * HW + hw0;

    if (tid < 128) sidx[tid] = g_idx[pix0 + tid];
    __syncthreads();

    float lsum = 0.f;
#pragma unroll 4
    for (int it = 0; it < (128 * EMB_DIM) / 256; it++) {
        int i = tid + it * 256;
        int p = i & 127;
        int c = i >> 7;
        int idx = sidx[p];
        float q = __ldg(&emb[(size_t)idx * EMB_DIM + c]);
        float xv = xbase[(size_t)c * HW + p];
        out[1 + ((size_t)b * EMB_DIM + c) * HW + hw0 + p] = q;
        float d = q - xv;
        lsum = fmaf(d, d, lsum);
    }
#pragma unroll
    for (int off = 16; off > 0; off >>= 1)
        lsum += __shfl_down_sync(0xffffffffu, lsum, off);
    if ((tid & 31) == 0) s_loss[tid >> 5] = (double)lsum;
    __syncthreads();
    if (tid == 0) {
        double tt = 0.0;
#pragma unroll
        for (int w = 0; w < 8; w++) tt += s_loss[w];
        atomicAdd(&g_loss, tt);
    }
}

__global__ void vq_finalize_kernel(float* __restrict__ out) {
    out[0] = (float)(g_loss * (1.0625 / 16777216.0));
}

extern "C" void kernel_launch(void* const* d_in, const int* in_sizes, int n_in,
                              void* d_out, int out_size) {
    const float* x = (const float*)d_in[0];
    const float* emb = (const float*)d_in[1];
    float* out = (float*)d_out;

    cudaFuncSetAttribute(vq_gemm_kernel,
                         cudaFuncAttributeMaxDynamicSharedMemorySize, GEMM_DSMEM);

    vq_esplit_kernel<<<NUM_EMB, 256>>>(emb);
    vq_etrans_kernel<<<EMB_DIM, 256>>>(emb);
    vq_enorm_kernel<<<NUM_EMB / 32, 256>>>(emb);
    vq_xsplit_kernel<<<NPIX / 128, 256>>>(x);
    vq_xnorm_kernel<<<NPIX / 256, 256>>>(x);
    vq_gemm_kernel<<<NPIX / 128, 256, GEMM_DSMEM>>>();
    vq_rescue_kernel<<<148, 256>>>(x);
    vq_writeback_kernel<<<NPIX / 128, 256>>>(x, emb, out);
    vq_finalize_kernel<<<1, 1>>>(out);
}

// round 13
// speedup vs baseline: 4.0292x; 1.0458x over previous
#include <cuda_runtime.h>
#include <cuda_bf16.h>
#include <cstdint>

// VQ-VAE quantizer: bf16-split HMMA screening (cp.async double-buffered,
// ldmatrix fragment loads) + exact-chain rescue, reproducing the JAX/XLA-CPU
// fp32 reference argmin bitwise.
//   x: [16, 256, 64, 64] f32   (d_in[0])
//   emb: [1024, 256] f32       (d_in[1])
//   out: [1 + 16*256*64*64] f32: out[0]=c_loss, out[1:]=quant_out (NCHW)

#define NUM_EMB 1024
#define EMB_DIM 256
#define HW 4096
#define NPIX 65536
#define KSPLIT 768              // [hi | hi | lo] x [hi | lo | hi]
#define MARGIN 1.5e-4f
#define STAGE_B 18432           // 128 rows x 72 halves x 2B
#define GEMM_DSMEM (4 * STAGE_B)
#define RESC_PIX 16

__device__ double g_loss;
__device__ float g_enorm[NUM_EMB];
__device__ float g_xnorm[NPIX];
__device__ int g_idx[NPIX];
__device__ int g_resc_count;
__device__ int g_resc[NPIX];
__device__ __nv_bfloat16 g_Xp[(size_t)NPIX * KSPLIT];   // [pixel][768]
__device__ __nv_bfloat16 g_Ep[NUM_EMB * KSPLIT];        // [code][768]
__device__ float g_EpT[EMB_DIM * NUM_EMB];              // [c][k] transposed emb

#define MMA16816(d, a0, a1, a2, a3, bb0, bb1) \
    asm volatile("mma.sync.aligned.m16n8k16.row.col.f32.bf16.bf16.f32 " \
                 "{%0,%1,%2,%3}, {%4,%5,%6,%7}, {%8,%9}, {%0,%1,%2,%3};" \
                 : "+f"((d)[0]), "+f"((d)[1]), "+f"((d)[2]), "+f"((d)[3]) \
                 : "r"(a0), "r"(a1), "r"(a2), "r"(a3), "r"(bb0), "r"(bb1))
#define LDSM4(r0, r1, r2, r3, addr) \
    asm volatile("ldmatrix.sync.aligned.m8n8.x4.shared.b16 {%0,%1,%2,%3}, [%4];" \
                 : "=r"(r0), "=r"(r1), "=r"(r2), "=r"(r3) : "r"(addr))
#define CPASYNC16(dst_u32, src) \
    asm volatile("cp.async.cg.shared.global [%0], [%1], 16;" \
                 :: "r"(dst_u32), "l"(src) : "memory")
#define CPCOMMIT() asm volatile("cp.async.commit_group;" ::: "memory")
#define CPWAIT1() asm volatile("cp.async.wait_group 1;" ::: "memory")
#define CPWAIT0() asm volatile("cp.async.wait_group 0;" ::: "memory")

__device__ __forceinline__ uint32_t smem_u32(const void* p) {
    uint32_t a;
    asm("{ .reg .u64 t; cvta.to.shared.u64 t, %1; cvt.u32.u64 %0, t; }" : "=r"(a) : "l"(p));
    return a;
}

// ---------------- reference-rounding helper ----------------
__device__ __forceinline__ float reduce8_pattern(const float S[8]) {
    float t02 = __fadd_rn(__fadd_rn(S[0], S[4]), __fadd_rn(S[2], S[6]));
    float t13 = __fadd_rn(__fadd_rn(S[1], S[5]), __fadd_rn(S[3], S[7]));
    return __fadd_rn(t02, t13);
}

// ---------------- kernel 1a: coalesced E split (+ zero accumulators) --------
__global__ void vq_esplit_kernel(const float* __restrict__ emb) {
    const int k = blockIdx.x;       // 1024 blocks
    const int c = threadIdx.x;      // 256 threads
    if (k == 0 && c == 0) { g_loss = 0.0; g_resc_count = 0; }
    float v = emb[(size_t)k * EMB_DIM + c];
    __nv_bfloat16 hi = __float2bfloat16_rn(v);
    __nv_bfloat16 lo = __float2bfloat16_rn(v - __bfloat162float(hi));
    __nv_bfloat16* er = g_Ep + (size_t)k * KSPLIT;
    er[c] = hi; er[256 + c] = lo; er[512 + c] = hi;
}

// ---------------- kernel 1b: transpose emb -> g_EpT[c][k] -------------------
__global__ void vq_etrans_kernel(const float* __restrict__ emb) {
    const int c = blockIdx.x;       // 256 blocks
#pragma unroll
    for (int q = 0; q < 4; q++) {
        int k = threadIdx.x + q * 256;
        g_EpT[c * NUM_EMB + k] = emb[(size_t)k * EMB_DIM + c];
    }
}

// ---------------- kernel 1c: ||e_k||^2, 8 lanes/code, exact XLA tree --------
__global__ void vq_enorm_kernel(const float* __restrict__ emb) {
    const int tid = threadIdx.x;
    const int gw = (blockIdx.x * blockDim.x + tid) >> 5;  // global warp 0..255
    const int lane = tid & 31;
    const int k = gw * 4 + (lane >> 3);
    const int r = lane & 7;
    const float* row = emb + (size_t)k * EMB_DIM;
    float S = 0.f;
#pragma unroll 8
    for (int j = 0; j < 32; j++) {
        float v = row[r + 8 * j];
        S = __fadd_rn(S, __fmul_rn(v, v));
    }
    float o = __shfl_down_sync(0xffffffffu, S, 4, 8);
    float T = __fadd_rn(S, o);
    o = __shfl_down_sync(0xffffffffu, T, 2, 8);
    float U = __fadd_rn(T, o);
    o = __shfl_down_sync(0xffffffffu, U, 1, 8);
    float R = __fadd_rn(U, o);
    if (r == 0) g_enorm[k] = R;
}

// ---------------- kernel 2: split X into [hi | hi | lo] row-major ----------
__global__ __launch_bounds__(256)
void vq_xsplit_kernel(const float* __restrict__ x) {
    __shared__ float xs[128 * 66];   // [p][c], stride 66
    const int tid = threadIdx.x;
    const int pix0 = blockIdx.x * 128;
    const int b = pix0 >> 12;
    const int hw0 = pix0 & (HW - 1);
    const float* xbase = x + ((size_t)b * EMB_DIM) * HW + hw0;

    for (int c0 = 0; c0 < EMB_DIM; c0 += 64) {
        __syncthreads();
#pragma unroll
        for (int it = 0; it < 32; it++) {
            int i = tid + it * 256;
            int p = i & 127, c = i >> 7;
            xs[p * 66 + c] = xbase[(size_t)(c0 + c) * HW + p];
        }
        __syncthreads();
#pragma unroll
        for (int it = 0; it < 16; it++) {
            int i = tid + it * 256;
            int p = i >> 5, cp = i & 31;
            float2 v = *(const float2*)&xs[p * 66 + 2 * cp];
            __nv_bfloat16 h0 = __float2bfloat16_rn(v.x);
            __nv_bfloat16 l0 = __float2bfloat16_rn(v.x - __bfloat162float(h0));
            __nv_bfloat16 h1 = __float2bfloat16_rn(v.y);
            __nv_bfloat16 l1 = __float2bfloat16_rn(v.y - __bfloat162float(h1));
            size_t row = (size_t)(pix0 + p) * KSPLIT;
            __nv_bfloat162 hh; hh.x = h0; hh.y = h1;
            __nv_bfloat162 ll; ll.x = l0; ll.y = l1;
            *(__nv_bfloat162*)&g_Xp[row + c0 + 2 * cp] = hh;
            *(__nv_bfloat162*)&g_Xp[row + 256 + c0 + 2 * cp] = hh;
            *(__nv_bfloat162*)&g_Xp[row + 512 + c0 + 2 * cp] = ll;
        }
    }
}

// ---------------- kernel 3: per-pixel ||x||^2 with reference pattern -------
__global__ __launch_bounds__(256)
void vq_xnorm_kernel(const float* __restrict__ x) {
    int p = blockIdx.x * 256 + threadIdx.x;
    int b = p >> 12;
    int hw = p & (HW - 1);
    const float* xb = x + ((size_t)b * EMB_DIM) * HW + hw;
    float S[8];
#pragma unroll
    for (int r = 0; r < 8; r++) S[r] = 0.f;
    for (int c = 0; c < EMB_DIM; c += 8)
#pragma unroll
        for (int r = 0; r < 8; r++) {
            float v = xb[(size_t)(c + r) * HW];
            S[r] = __fadd_rn(S[r], __fmul_rn(v, v));
        }
    g_xnorm[p] = reduce8_pattern(S);
}

// ---------------- kernel 4: HMMA GEMM screening + argmin -------------------
// CTA: 128 pixels x 1024 codes; 8 code tiles of 128; K'=768 in 12 chunks of 64.
// Warps: 4(M) x 2(N). Fragments via ldmatrix.x4 (6 LDSM/kf vs 24 scalar LDS).
__global__ __launch_bounds__(256, 2)
void vq_gemm_kernel() {
    extern __shared__ __align__(16) char dsm[];
    __nv_bfloat16* As = (__nv_bfloat16*)dsm;                    // 2 stages
    __nv_bfloat16* Bs = (__nv_bfloat16*)(dsm + 2 * STAGE_B);    // 2 stages
    __shared__ float mb1[128];
    __shared__ float mb2[128];
    __shared__ int mi1s[128];

    const int tid = threadIdx.x;
    const int lane = tid & 31;
    const int wid = tid >> 5;
    const int wm = wid & 3;
    const int wn = wid >> 2;
    const int g = lane >> 2;
    const int t = lane & 3;
    const int pix0 = blockIdx.x * 128;

    const uint32_t sA = smem_u32(As);
    const uint32_t sB = smem_u32(Bs);
    const char* XpB = (const char*)g_Xp;
    const char* EpB = (const char*)g_Ep;

    // ldmatrix per-lane base addresses (byte offsets; row stride 144B).
    // A groups: g0=(rows+0,col0)->a0, g1=(rows+8,col0)->a1,
    //           g2=(rows+0,col16B)->a2, g3=(rows+8,col16B)->a3
    // B groups: g0=(ni rows,col0)->bb0, g1=(ni rows,col16B)->bb1,
    //           g2=(ni+1 rows,col0), g3=(ni+1 rows,col16B)
    const int lh = lane & 7;
    const int l8 = (lane >> 3) & 1;
    const int l16 = (lane >> 4) & 1;
    const uint32_t aoff = (uint32_t)((32 * wm + lh + 8 * l8) * 144 + l16 * 16);
    const uint32_t boff = (uint32_t)((64 * wn + lh + 8 * l16) * 144 + l8 * 16);

    int frow[4], fcj[4];
#pragma unroll
    for (int it = 0; it < 4; it++) {
        int id = tid + it * 256;
        frow[it] = id >> 3;
        fcj[it] = id & 7;
    }

    float a_p[4];
    int rowOf[4];
#pragma unroll
    for (int s = 0; s < 4; s++) {
        rowOf[s] = 32 * wm + 16 * (s >> 1) + 8 * (s & 1) + g;
        a_p[s] = g_xnorm[pix0 + rowOf[s]];
    }
    float b1[4], b2[4];
    int i1[4];
#pragma unroll
    for (int s = 0; s < 4; s++) { b1[s] = 3.4e38f; b2[s] = 3.4e38f; i1[s] = 0; }

    for (int tile = 0; tile < 8; tile++) {
        const int n0 = tile * 128;
        float acc[2][8][4];
#pragma unroll
        for (int mi = 0; mi < 2; mi++)
#pragma unroll
            for (int ni = 0; ni < 8; ni++)
#pragma unroll
                for (int q = 0; q < 4; q++) acc[mi][ni][q] = 0.f;

#pragma unroll
        for (int it = 0; it < 4; it++) {
            uint32_t doff = (uint32_t)(frow[it] * 144 + fcj[it] * 16);
            CPASYNC16(sA + doff, XpB + ((size_t)(pix0 + frow[it]) * 768 + fcj[it] * 8) * 2);
            CPASYNC16(sB + doff, EpB + ((size_t)(n0 + frow[it]) * 768 + fcj[it] * 8) * 2);
        }
        CPCOMMIT();

        for (int kc = 0; kc < 12; kc++) {
            const int st = kc & 1;
            if (kc + 1 < 12) {
                const int st2 = st ^ 1;
#pragma unroll
                for (int it = 0; it < 4; it++) {
                    uint32_t doff = (uint32_t)(st2 * STAGE_B + frow[it] * 144 + fcj[it] * 16);
                    size_t koff = (size_t)(kc + 1) * 64 + fcj[it] * 8;
                    CPASYNC16(sA + doff, XpB + ((size_t)(pix0 + frow[it]) * 768 + koff) * 2);
                    CPASYNC16(sB + doff, EpB + ((size_t)(n0 + frow[it]) * 768 + koff) * 2);
                }
                CPCOMMIT();
                CPWAIT1();
            } else {
                CPWAIT0();
            }
            __syncthreads();

            const uint32_t stB = (uint32_t)(st * STAGE_B);
#pragma unroll
            for (int kf = 0; kf < 4; kf++) {
                uint32_t a[2][4];
#pragma unroll
                for (int mi = 0; mi < 2; mi++)
                    LDSM4(a[mi][0], a[mi][1], a[mi][2], a[mi][3],
                          sA + stB + aoff + (uint32_t)(mi * 2304 + kf * 32));
#pragma unroll
                for (int np = 0; np < 4; np++) {
                    uint32_t bb0, bb1, bb2, bb3;
                    LDSM4(bb0, bb1, bb2, bb3,
                          sB + stB + boff + (uint32_t)(np * 2304 + kf * 32));
#pragma unroll
                    for (int mi = 0; mi < 2; mi++) {
                        MMA16816(acc[mi][2 * np], a[mi][0], a[mi][1], a[mi][2], a[mi][3], bb0, bb1);
                        MMA16816(acc[mi][2 * np + 1], a[mi][0], a[mi][1], a[mi][2], a[mi][3], bb2, bb3);
                    }
                }
            }
            __syncthreads();
        }

        // Epilogue: reference-rounded scores.
        // c-frag: q0=(g,2t) q1=(g,2t+1) q2=(g+8,2t) q3=(g+8,2t+1); slot s=2mi+(q>>1).
#pragma unroll
        for (int ni = 0; ni < 8; ni++) {
            int kb = n0 + 64 * wn + 8 * ni + 2 * t;
            float c0 = __ldg(&g_enorm[kb]);
            float c1 = __ldg(&g_enorm[kb + 1]);
#pragma unroll
            for (int mi = 0; mi < 2; mi++) {
#pragma unroll
                for (int q = 0; q < 4; q++) {
                    int s = 2 * mi + (q >> 1);
                    float bv = acc[mi][ni][q];
                    int k = kb + (q & 1);
                    float cn = (q & 1) ? c1 : c0;
                    float sc = __fadd_rn(__fsub_rn(a_p[s], __fmul_rn(2.0f, bv)), cn);
                    if (sc < b1[s]) { b2[s] = b1[s]; b1[s] = sc; i1[s] = k; }
                    else if (sc < b2[s]) { b2[s] = sc; }
                }
            }
        }
    }

#pragma unroll
    for (int s = 0; s < 4; s++) {
        float x1 = b1[s], x2 = b2[s];
        int xi = i1[s];
#pragma unroll
        for (int off = 2; off > 0; off >>= 1) {
            float o1 = __shfl_down_sync(0xffffffffu, x1, off, 4);
            float o2 = __shfl_down_sync(0xffffffffu, x2, off, 4);
            int oi = __shfl_down_sync(0xffffffffu, xi, off, 4);
            float n2 = fminf(fmaxf(x1, o1), fminf(x2, o2));
            if (o1 < x1 || (o1 == x1 && oi < xi)) { x1 = o1; xi = oi; }
            x2 = n2;
        }
        b1[s] = x1; b2[s] = x2; i1[s] = xi;
    }
    if (wn == 0 && t == 0) {
#pragma unroll
        for (int s = 0; s < 4; s++) {
            mb1[rowOf[s]] = b1[s];
            mb2[rowOf[s]] = b2[s];
            mi1s[rowOf[s]] = i1[s];
        }
    }
    __syncthreads();
    if (wn == 1 && t == 0) {
#pragma unroll
        for (int s = 0; s < 4; s++) {
            int r = rowOf[s];
            float o1 = mb1[r], o2 = mb2[r];
            int oi = mi1s[r];
            float n2 = fminf(fmaxf(b1[s], o1), fminf(b2[s], o2));
            float n1;
            int ni_;
            if (o1 < b1[s] || (o1 == b1[s] && oi < i1[s])) { n1 = o1; ni_ = oi; }
            else { n1 = b1[s]; ni_ = i1[s]; }
            int p = pix0 + r;
            g_idx[p] = ni_;
            if (n2 - n1 < MARGIN) {
                int rr = atomicAdd(&g_resc_count, 1);
                g_resc[rr] = p;
            }
        }
    }
}

// ---------------- kernel 5: exact rescue, 16 pixels/block, coalesced -------
__global__ __launch_bounds__(256)
void vq_rescue_kernel(const float* __restrict__ x) {
    __shared__ float xsm[RESC_PIX * 256];
    __shared__ int plist[RESC_PIX];
    __shared__ float rbs[RESC_PIX * 8];
    __shared__ int rbk[RESC_PIX * 8];
    const int tid = threadIdx.x;
    const int lane = tid & 31, wid = tid >> 5;
    const int cnt = g_resc_count;

    for (int base = blockIdx.x * RESC_PIX; base < cnt; base += gridDim.x * RESC_PIX) {
        const int nv = min(RESC_PIX, cnt - base);
        __syncthreads();
        if (tid < RESC_PIX)
            plist[tid] = g_resc[base + ((tid < nv) ? tid : 0)];
        __syncthreads();
        for (int j = wid; j < RESC_PIX; j += 8) {
            int p = plist[j];
            int b = p >> 12, hw = p & (HW - 1);
            const float* xb = x + ((size_t)b * EMB_DIM) * HW + hw;
            for (int c = lane; c < EMB_DIM; c += 32)
                xsm[j * 256 + c] = xb[(size_t)c * HW];
        }
        __syncthreads();

        float best[RESC_PIX];
        int bidx[RESC_PIX];
#pragma unroll
        for (int j = 0; j < RESC_PIX; j++) { best[j] = 3.4e38f; bidx[j] = 0; }

#pragma unroll
        for (int pass = 0; pass < 2; pass++) {
            const int k0 = tid + (2 * pass) * 256;
            const int k1 = tid + (2 * pass + 1) * 256;
            float acc0[RESC_PIX], acc1[RESC_PIX];
#pragma unroll
            for (int j = 0; j < RESC_PIX; j++) { acc0[j] = 0.f; acc1[j] = 0.f; }
            for (int c = 0; c < EMB_DIM; c++) {
                float e0 = g_EpT[c * NUM_EMB + k0];
                float e1 = g_EpT[c * NUM_EMB + k1];
#pragma unroll
                for (int j = 0; j < RESC_PIX; j++) {
                    float xv = xsm[j * 256 + c];
                    acc0[j] = fmaf(xv, e0, acc0[j]);
                    acc1[j] = fmaf(xv, e1, acc1[j]);
                }
            }
            float en0 = g_enorm[k0], en1 = g_enorm[k1];
#pragma unroll
            for (int j = 0; j < RESC_PIX; j++) {
                float a = g_xnorm[plist[j]];
                float s0 = __fadd_rn(__fsub_rn(a, __fmul_rn(2.0f, acc0[j])), en0);
                float s1 = __fadd_rn(__fsub_rn(a, __fmul_rn(2.0f, acc1[j])), en1);
                if (s0 < best[j]) { best[j] = s0; bidx[j] = k0; }
                if (s1 < best[j]) { best[j] = s1; bidx[j] = k1; }
            }
        }
#pragma unroll
        for (int j = 0; j < RESC_PIX; j++) {
            float s = best[j];
            int k = bidx[j];
#pragma unroll
            for (int off = 16; off > 0; off >>= 1) {
                float so = __shfl_down_sync(0xffffffffu, s, off);
                int ko = __shfl_down_sync(0xffffffffu, k, off);
                if (so < s || (so == s && ko < k)) { s = so; k = ko; }
            }
            if (lane == 0) { rbs[j * 8 + wid] = s; rbk[j * 8 + wid] = k; }
        }
        __syncthreads();
        if (tid < nv) {
            float s = rbs[tid * 8];
            int k = rbk[tid * 8];
#pragma unroll
            for (int w = 1; w < 8; w++) {
                float so = rbs[tid * 8 + w];
                int ko = rbk[tid * 8 + w];
                if (so < s || (so == s && ko < k)) { s = so; k = ko; }
            }
            g_idx[plist[tid]] = k;
        }
    }
}

// ---------------- kernel 6: gather/writeback + loss ----------------
__global__ __launch_bounds__(256)
void vq_writeback_kernel(const float* __restrict__ x,
                         const float* __restrict__ emb,
                         float* __restrict__ out) {
    __shared__ int sidx[128];
    __shared__ double s_loss[8];
    const int tid = threadIdx.x;
    const int pix0 = blockIdx.x * 128;
    const int b = pix0 >> 12;
    const int hw0 = pix0 & (HW - 1);
    const float* xbase = x + ((size_t)b * EMB_DIM) * HW + hw0;

    if (tid < 128) sidx[tid] = g_idx[pix0 + tid];
    __syncthreads();

    float lsum = 0.f;
#pragma unroll 4
    for (int it = 0; it < (128 * EMB_DIM) / 256; it++) {
        int i = tid + it * 256;
        int p = i & 127;
        int c = i >> 7;
        int idx = sidx[p];
        float q = __ldg(&emb[(size_t)idx * EMB_DIM + c]);
        float xv = xbase[(size_t)c * HW + p];
        out[1 + ((size_t)b * EMB_DIM + c) * HW + hw0 + p] = q;
        float d = q - xv;
        lsum = fmaf(d, d, lsum);
    }
#pragma unroll
    for (int off = 16; off > 0; off >>= 1)
        lsum += __shfl_down_sync(0xffffffffu, lsum, off);
    if ((tid & 31) == 0) s_loss[tid >> 5] = (double)lsum;
    __syncthreads();
    if (tid == 0) {
        double tt = 0.0;
#pragma unroll
        for (int w = 0; w < 8; w++) tt += s_loss[w];
        atomicAdd(&g_loss, tt);
    }
}

__global__ void vq_finalize_kernel(float* __restrict__ out) {
    out[0] = (float)(g_loss * (1.0625 / 16777216.0));
}

extern "C" void kernel_launch(void* const* d_in, const int* in_sizes, int n_in,
                              void* d_out, int out_size) {
    const float* x = (const float*)d_in[0];
    const float* emb = (const float*)d_in[1];
    float* out = (float*)d_out;

    cudaFuncSetAttribute(vq_gemm_kernel,
                         cudaFuncAttributeMaxDynamicSharedMemorySize, GEMM_DSMEM);

    vq_esplit_kernel<<<NUM_EMB, 256>>>(emb);
    vq_etrans_kernel<<<EMB_DIM, 256>>>(emb);
    vq_enorm_kernel<<<NUM_EMB / 32, 256>>>(emb);
    vq_xsplit_kernel<<<NPIX / 128, 256>>>(x);
    vq_xnorm_kernel<<<NPIX / 256, 256>>>(x);
    vq_gemm_kernel<<<NPIX / 128, 256, GEMM_DSMEM>>>();
    vq_rescue_kernel<<<148, 256>>>(x);
    vq_writeback_kernel<<<NPIX / 128, 256>>>(x, emb, out);
    vq_finalize_kernel<<<1, 1>>>(out);
}

// round 14
// speedup vs baseline: 4.4291x; 1.0993x over previous
#include <cuda_runtime.h>
#include <cuda_bf16.h>
#include <cstdint>

// VQ-VAE quantizer: bf16-split HMMA screening (flattened 3-stage cp.async
// pipeline, ldmatrix fragments) + exact-chain rescue, reproducing the
// JAX/XLA-CPU fp32 reference argmin bitwise.
//   x: [16, 256, 64, 64] f32   (d_in[0])
//   emb: [1024, 256] f32       (d_in[1])
//   out: [1 + 16*256*64*64] f32: out[0]=c_loss, out[1:]=quant_out (NCHW)

#define NUM_EMB 1024
#define EMB_DIM 256
#define HW 4096
#define NPIX 65536
#define KSPLIT 768              // [hi | hi | lo] x [hi | lo | hi]
#define MARGIN 1.5e-4f
#define STAGE_B 18432           // 128 rows x 72 halves x 2B
#define GEMM_DSMEM (6 * STAGE_B)   // 3 stages A + 3 stages B = 108 KB
#define RESC_PIX 16

__device__ double g_loss;
__device__ float g_enorm[NUM_EMB];
__device__ float g_xnorm[NPIX];
__device__ int g_idx[NPIX];
__device__ int g_resc_count;
__device__ int g_resc[NPIX];
__device__ __nv_bfloat16 g_Xp[(size_t)NPIX * KSPLIT];   // [pixel][768]
__device__ __nv_bfloat16 g_Ep[NUM_EMB * KSPLIT];        // [code][768]
__device__ float g_EpT[EMB_DIM * NUM_EMB];              // [c][k] transposed emb

#define MMA16816(d, a0, a1, a2, a3, bb0, bb1) \
    asm volatile("mma.sync.aligned.m16n8k16.row.col.f32.bf16.bf16.f32 " \
                 "{%0,%1,%2,%3}, {%4,%5,%6,%7}, {%8,%9}, {%0,%1,%2,%3};" \
                 : "+f"((d)[0]), "+f"((d)[1]), "+f"((d)[2]), "+f"((d)[3]) \
                 : "r"(a0), "r"(a1), "r"(a2), "r"(a3), "r"(bb0), "r"(bb1))
#define LDSM4(r0, r1, r2, r3, addr) \
    asm volatile("ldmatrix.sync.aligned.m8n8.x4.shared.b16 {%0,%1,%2,%3}, [%4];" \
                 : "=r"(r0), "=r"(r1), "=r"(r2), "=r"(r3) : "r"(addr))
#define CPASYNC16(dst_u32, src) \
    asm volatile("cp.async.cg.shared.global [%0], [%1], 16;" \
                 :: "r"(dst_u32), "l"(src) : "memory")
#define CPCOMMIT() asm volatile("cp.async.commit_group;" ::: "memory")
#define CPWAIT1() asm volatile("cp.async.wait_group 1;" ::: "memory")
#define CPWAIT0() asm volatile("cp.async.wait_group 0;" ::: "memory")

__device__ __forceinline__ uint32_t smem_u32(const void* p) {
    uint32_t a;
    asm("{ .reg .u64 t; cvta.to.shared.u64 t, %1; cvt.u32.u64 %0, t; }" : "=r"(a) : "l"(p));
    return a;
}

// ---------------- kernel 1a: coalesced E split (+ zero accumulators) --------
__global__ void vq_esplit_kernel(const float* __restrict__ emb) {
    const int k = blockIdx.x;       // 1024 blocks
    const int c = threadIdx.x;      // 256 threads
    if (k == 0 && c == 0) { g_loss = 0.0; g_resc_count = 0; }
    float v = emb[(size_t)k * EMB_DIM + c];
    __nv_bfloat16 hi = __float2bfloat16_rn(v);
    __nv_bfloat16 lo = __float2bfloat16_rn(v - __bfloat162float(hi));
    __nv_bfloat16* er = g_Ep + (size_t)k * KSPLIT;
    er[c] = hi; er[256 + c] = lo; er[512 + c] = hi;
}

// ---------------- kernel 1b: transpose emb -> g_EpT[c][k] -------------------
__global__ void vq_etrans_kernel(const float* __restrict__ emb) {
    const int c = blockIdx.x;       // 256 blocks
#pragma unroll
    for (int q = 0; q < 4; q++) {
        int k = threadIdx.x + q * 256;
        g_EpT[c * NUM_EMB + k] = emb[(size_t)k * EMB_DIM + c];
    }
}

// ---------------- kernel 1c: ||e_k||^2, 8 lanes/code, exact XLA tree --------
__global__ void vq_enorm_kernel(const float* __restrict__ emb) {
    const int tid = threadIdx.x;
    const int gw = (blockIdx.x * blockDim.x + tid) >> 5;  // global warp 0..255
    const int lane = tid & 31;
    const int k = gw * 4 + (lane >> 3);
    const int r = lane & 7;
    const float* row = emb + (size_t)k * EMB_DIM;
    float S = 0.f;
#pragma unroll 8
    for (int j = 0; j < 32; j++) {
        float v = row[r + 8 * j];
        S = __fadd_rn(S, __fmul_rn(v, v));
    }
    float o = __shfl_down_sync(0xffffffffu, S, 4, 8);
    float T = __fadd_rn(S, o);
    o = __shfl_down_sync(0xffffffffu, T, 2, 8);
    float U = __fadd_rn(T, o);
    o = __shfl_down_sync(0xffffffffu, U, 1, 8);
    float R = __fadd_rn(U, o);
    if (r == 0) g_enorm[k] = R;
}

// ---------------- kernel 2: split X + fused ||x||^2 (XLA pattern) ----------
// Same staging as before; additionally accumulates S_{p,r} = sum of fl(x^2)
// over c==r (mod 8) ascending, reduced with the exact XLA shfl tree:
// ((S0+S4)+(S2+S6)) + ((S1+S5)+(S3+S7)).
__global__ __launch_bounds__(256)
void vq_xsplit_kernel(const float* __restrict__ x) {
    __shared__ float xs[128 * 66];   // [p][c], stride 66
    const int tid = threadIdx.x;
    const int pix0 = blockIdx.x * 128;
    const int b = pix0 >> 12;
    const int hw0 = pix0 & (HW - 1);
    const float* xbase = x + ((size_t)b * EMB_DIM) * HW + hw0;
    const int r = tid & 7;

    float S4[4];
#pragma unroll
    for (int sl = 0; sl < 4; sl++) S4[sl] = 0.f;

    for (int c0 = 0; c0 < EMB_DIM; c0 += 64) {
        __syncthreads();
#pragma unroll
        for (int it = 0; it < 32; it++) {
            int i = tid + it * 256;
            int p = i & 127, c = i >> 7;
            xs[p * 66 + c] = xbase[(size_t)(c0 + c) * HW + p];
        }
        __syncthreads();
#pragma unroll
        for (int it = 0; it < 16; it++) {
            int i = tid + it * 256;
            int p = i >> 5, cp = i & 31;
            float2 v = *(const float2*)&xs[p * 66 + 2 * cp];
            __nv_bfloat16 h0 = __float2bfloat16_rn(v.x);
            __nv_bfloat16 l0 = __float2bfloat16_rn(v.x - __bfloat162float(h0));
            __nv_bfloat16 h1 = __float2bfloat16_rn(v.y);
            __nv_bfloat16 l1 = __float2bfloat16_rn(v.y - __bfloat162float(h1));
            size_t row = (size_t)(pix0 + p) * KSPLIT;
            __nv_bfloat162 hh; hh.x = h0; hh.y = h1;
            __nv_bfloat162 ll; ll.x = l0; ll.y = l1;
            *(__nv_bfloat162*)&g_Xp[row + c0 + 2 * cp] = hh;
            *(__nv_bfloat162*)&g_Xp[row + 256 + c0 + 2 * cp] = hh;
            *(__nv_bfloat162*)&g_Xp[row + 512 + c0 + 2 * cp] = ll;
        }
        // fused norm accumulation: thread owns (p = tid>>3 + 32*sl, r = tid&7)
#pragma unroll
        for (int sl = 0; sl < 4; sl++) {
            int p = (tid >> 3) + 32 * sl;
            const float* row = &xs[p * 66];
#pragma unroll
            for (int j = 0; j < 8; j++) {
                float v = row[r + 8 * j];
                S4[sl] = __fadd_rn(S4[sl], __fmul_rn(v, v));
            }
        }
    }
    // exact XLA tree across the 8 r-lanes (threads 8q..8q+7 adjacent in warp)
#pragma unroll
    for (int sl = 0; sl < 4; sl++) {
        float S = S4[sl];
        float o = __shfl_down_sync(0xffffffffu, S, 4, 8);
        float T = __fadd_rn(S, o);
        o = __shfl_down_sync(0xffffffffu, T, 2, 8);
        float U = __fadd_rn(T, o);
        o = __shfl_down_sync(0xffffffffu, U, 1, 8);
        float R = __fadd_rn(U, o);
        if (r == 0) g_xnorm[pix0 + (tid >> 3) + 32 * sl] = R;
    }
}

// ---------------- kernel 4: HMMA GEMM screening + argmin -------------------
// Flattened 96-chunk mainloop, 3 smem stages, ONE barrier per chunk.
// Per chunk m: tile=m/12, kc=m%12, stage=m%3.
__global__ __launch_bounds__(256, 2)
void vq_gemm_kernel() {
    extern __shared__ __align__(16) char dsm[];
    __nv_bfloat16* As = (__nv_bfloat16*)dsm;                    // 3 stages
    __nv_bfloat16* Bs = (__nv_bfloat16*)(dsm + 3 * STAGE_B);    // 3 stages
    __shared__ float mb1[128];
    __shared__ float mb2[128];
    __shared__ int mi1s[128];

    const int tid = threadIdx.x;
    const int lane = tid & 31;
    const int wid = tid >> 5;
    const int wm = wid & 3;
    const int wn = wid >> 2;
    const int g = lane >> 2;
    const int t = lane & 3;
    const int pix0 = blockIdx.x * 128;

    const uint32_t sA = smem_u32(As);
    const uint32_t sB = smem_u32(Bs);
    const char* XpB = (const char*)g_Xp;
    const char* EpB = (const char*)g_Ep;

    const int lh = lane & 7;
    const int l8 = (lane >> 3) & 1;
    const int l16 = (lane >> 4) & 1;
    const uint32_t aoff = (uint32_t)((32 * wm + lh + 8 * l8) * 144 + l16 * 16);
    const uint32_t boff = (uint32_t)((64 * wn + lh + 8 * l16) * 144 + l8 * 16);

    int frow[4], fcj[4];
#pragma unroll
    for (int it = 0; it < 4; it++) {
        int id = tid + it * 256;
        frow[it] = id >> 3;
        fcj[it] = id & 7;
    }

    float a_p[4];
    int rowOf[4];
#pragma unroll
    for (int s = 0; s < 4; s++) {
        rowOf[s] = 32 * wm + 16 * (s >> 1) + 8 * (s & 1) + g;
        a_p[s] = g_xnorm[pix0 + rowOf[s]];
    }
    float b1[4], b2[4];
    int i1[4];
#pragma unroll
    for (int s = 0; s < 4; s++) { b1[s] = 3.4e38f; b2[s] = 3.4e38f; i1[s] = 0; }

    float acc[2][8][4];

    // prologue: prefetch chunks 0, 1 (separate commit groups)
#pragma unroll
    for (int m = 0; m < 2; m++) {
        const int tile2 = 0, kc2 = m;
#pragma unroll
        for (int it = 0; it < 4; it++) {
            uint32_t doff = (uint32_t)(m * STAGE_B + frow[it] * 144 + fcj[it] * 16);
            size_t koff = (size_t)kc2 * 64 + fcj[it] * 8;
            CPASYNC16(sA + doff, XpB + ((size_t)(pix0 + frow[it]) * 768 + koff) * 2);
            CPASYNC16(sB + doff, EpB + ((size_t)(tile2 * 128 + frow[it]) * 768 + koff) * 2);
        }
        CPCOMMIT();
    }

    for (int m = 0; m < 96; m++) {
        const int kc = m % 12;
        const uint32_t stB = (uint32_t)((m % 3) * STAGE_B);

        if (kc == 0) {
#pragma unroll
            for (int mi = 0; mi < 2; mi++)
#pragma unroll
                for (int ni = 0; ni < 8; ni++)
#pragma unroll
                    for (int q = 0; q < 4; q++) acc[mi][ni][q] = 0.f;
        }

        if (m == 95) { CPWAIT0(); } else { CPWAIT1(); }
        __syncthreads();

        // compute chunk m from stage m%3
#pragma unroll
        for (int kf = 0; kf < 4; kf++) {
            uint32_t a[2][4];
#pragma unroll
            for (int mi = 0; mi < 2; mi++)
                LDSM4(a[mi][0], a[mi][1], a[mi][2], a[mi][3],
                      sA + stB + aoff + (uint32_t)(mi * 2304 + kf * 32));
#pragma unroll
            for (int np = 0; np < 4; np++) {
                uint32_t bb0, bb1, bb2, bb3;
                LDSM4(bb0, bb1, bb2, bb3,
                      sB + stB + boff + (uint32_t)(np * 2304 + kf * 32));
#pragma unroll
                for (int mi = 0; mi < 2; mi++) {
                    MMA16816(acc[mi][2 * np], a[mi][0], a[mi][1], a[mi][2], a[mi][3], bb0, bb1);
                    MMA16816(acc[mi][2 * np + 1], a[mi][0], a[mi][1], a[mi][2], a[mi][3], bb2, bb3);
                }
            }
        }

        // prefetch chunk m+2 into stage (m+2)%3 (safe: all warps passed the
        // barrier above, hence finished reading stage (m-1)%3 == (m+2)%3)
        if (m + 2 < 96) {
            const int m2 = m + 2;
            const int tile2 = m2 / 12, kc2 = m2 % 12;
            const uint32_t st2 = (uint32_t)((m2 % 3) * STAGE_B);
#pragma unroll
            for (int it = 0; it < 4; it++) {
                uint32_t doff = st2 + (uint32_t)(frow[it] * 144 + fcj[it] * 16);
                size_t koff = (size_t)kc2 * 64 + fcj[it] * 8;
                CPASYNC16(sA + doff, XpB + ((size_t)(pix0 + frow[it]) * 768 + koff) * 2);
                CPASYNC16(sB + doff, EpB + ((size_t)(tile2 * 128 + frow[it]) * 768 + koff) * 2);
            }
            CPCOMMIT();
        }

        if (kc == 11) {
            // Epilogue for this tile: reference-rounded scores.
            // c-frag: q0=(g,2t) q1=(g,2t+1) q2=(g+8,2t) q3=(g+8,2t+1); s=2mi+(q>>1).
            const int n0 = (m / 12) * 128;
#pragma unroll
            for (int ni = 0; ni < 8; ni++) {
                int kb = n0 + 64 * wn + 8 * ni + 2 * t;
                float c0 = __ldg(&g_enorm[kb]);
                float c1 = __ldg(&g_enorm[kb + 1]);
#pragma unroll
                for (int mi = 0; mi < 2; mi++) {
#pragma unroll
                    for (int q = 0; q < 4; q++) {
                        int s = 2 * mi + (q >> 1);
                        float bv = acc[mi][ni][q];
                        int k = kb + (q & 1);
                        float cn = (q & 1) ? c1 : c0;
                        float sc = __fadd_rn(__fsub_rn(a_p[s], __fmul_rn(2.0f, bv)), cn);
                        if (sc < b1[s]) { b2[s] = b1[s]; b1[s] = sc; i1[s] = k; }
                        else if (sc < b2[s]) { b2[s] = sc; }
                    }
                }
            }
        }
    }

#pragma unroll
    for (int s = 0; s < 4; s++) {
        float x1 = b1[s], x2 = b2[s];
        int xi = i1[s];
#pragma unroll
        for (int off = 2; off > 0; off >>= 1) {
            float o1 = __shfl_down_sync(0xffffffffu, x1, off, 4);
            float o2 = __shfl_down_sync(0xffffffffu, x2, off, 4);
            int oi = __shfl_down_sync(0xffffffffu, xi, off, 4);
            float n2 = fminf(fmaxf(x1, o1), fminf(x2, o2));
            if (o1 < x1 || (o1 == x1 && oi < xi)) { x1 = o1; xi = oi; }
            x2 = n2;
        }
        b1[s] = x1; b2[s] = x2; i1[s] = xi;
    }
    if (wn == 0 && t == 0) {
#pragma unroll
        for (int s = 0; s < 4; s++) {
            mb1[rowOf[s]] = b1[s];
            mb2[rowOf[s]] = b2[s];
            mi1s[rowOf[s]] = i1[s];
        }
    }
    __syncthreads();
    if (wn == 1 && t == 0) {
#pragma unroll
        for (int s = 0; s < 4; s++) {
            int r = rowOf[s];
            float o1 = mb1[r], o2 = mb2[r];
            int oi = mi1s[r];
            float n2 = fminf(fmaxf(b1[s], o1), fminf(b2[s], o2));
            float n1;
            int ni_;
            if (o1 < b1[s] || (o1 == b1[s] && oi < i1[s])) { n1 = o1; ni_ = oi; }
            else { n1 = b1[s]; ni_ = i1[s]; }
            int p = pix0 + r;
            g_idx[p] = ni_;
            if (n2 - n1 < MARGIN) {
                int rr = atomicAdd(&g_resc_count, 1);
                g_resc[rr] = p;
            }
        }
    }
}

// ---------------- kernel 5: exact rescue, 16 pixels/block, coalesced -------
__global__ __launch_bounds__(256)
void vq_rescue_kernel(const float* __restrict__ x) {
    __shared__ float xsm[RESC_PIX * 256];
    __shared__ int plist[RESC_PIX];
    __shared__ float rbs[RESC_PIX * 8];
    __shared__ int rbk[RESC_PIX * 8];
    const int tid = threadIdx.x;
    const int lane = tid & 31, wid = tid >> 5;
    const int cnt = g_resc_count;

    for (int base = blockIdx.x * RESC_PIX; base < cnt; base += gridDim.x * RESC_PIX) {
        const int nv = min(RESC_PIX, cnt - base);
        __syncthreads();
        if (tid < RESC_PIX)
            plist[tid] = g_resc[base + ((tid < nv) ? tid : 0)];
        __syncthreads();
        for (int j = wid; j < RESC_PIX; j += 8) {
            int p = plist[j];
            int b = p >> 12, hw = p & (HW - 1);
            const float* xb = x + ((size_t)b * EMB_DIM) * HW + hw;
            for (int c = lane; c < EMB_DIM; c += 32)
                xsm[j * 256 + c] = xb[(size_t)c * HW];
        }
        __syncthreads();

        float best[RESC_PIX];
        int bidx[RESC_PIX];
#pragma unroll
        for (int j = 0; j < RESC_PIX; j++) { best[j] = 3.4e38f; bidx[j] = 0; }

#pragma unroll
        for (int pass = 0; pass < 2; pass++) {
            const int k0 = tid + (2 * pass) * 256;
            const int k1 = tid + (2 * pass + 1) * 256;
            float acc0[RESC_PIX], acc1[RESC_PIX];
#pragma unroll
            for (int j = 0; j < RESC_PIX; j++) { acc0[j] = 0.f; acc1[j] = 0.f; }
            for (int c = 0; c < EMB_DIM; c++) {
                float e0 = g_EpT[c * NUM_EMB + k0];
                float e1 = g_EpT[c * NUM_EMB + k1];
#pragma unroll
                for (int j = 0; j < RESC_PIX; j++) {
                    float xv = xsm[j * 256 + c];
                    acc0[j] = fmaf(xv, e0, acc0[j]);
                    acc1[j] = fmaf(xv, e1, acc1[j]);
                }
            }
            float en0 = g_enorm[k0], en1 = g_enorm[k1];
#pragma unroll
            for (int j = 0; j < RESC_PIX; j++) {
                float a = g_xnorm[plist[j]];
                float s0 = __fadd_rn(__fsub_rn(a, __fmul_rn(2.0f, acc0[j])), en0);
                float s1 = __fadd_rn(__fsub_rn(a, __fmul_rn(2.0f, acc1[j])), en1);
                if (s0 < best[j]) { best[j] = s0; bidx[j] = k0; }
                if (s1 < best[j]) { best[j] = s1; bidx[j] = k1; }
            }
        }
#pragma unroll
        for (int j = 0; j < RESC_PIX; j++) {
            float s = best[j];
            int k = bidx[j];
#pragma unroll
            for (int off = 16; off > 0; off >>= 1) {
                float so = __shfl_down_sync(0xffffffffu, s, off);
                int ko = __shfl_down_sync(0xffffffffu, k, off);
                if (so < s || (so == s && ko < k)) { s = so; k = ko; }
            }
            if (lane == 0) { rbs[j * 8 + wid] = s; rbk[j * 8 + wid] = k; }
        }
        __syncthreads();
        if (tid < nv) {
            float s = rbs[tid * 8];
            int k = rbk[tid * 8];
#pragma unroll
            for (int w = 1; w < 8; w++) {
                float so = rbs[tid * 8 + w];
                int ko = rbk[tid * 8 + w];
                if (so < s || (so == s && ko < k)) { s = so; k = ko; }
            }
            g_idx[plist[tid]] = k;
        }
    }
}

// ---------------- kernel 6: gather/writeback + loss ----------------
__global__ __launch_bounds__(256)
void vq_writeback_kernel(const float* __restrict__ x,
                         const float* __restrict__ emb,
                         float* __restrict__ out) {
    __shared__ int sidx[128];
    __shared__ double s_loss[8];
    const int tid = threadIdx.x;
    const int pix0 = blockIdx.x * 128;
    const int b = pix0 >> 12;
    const int hw0 = pix0 & (HW - 1);
    const float* xbase = x + ((size_t)b * EMB_DIM) * HW + hw0;

    if (tid < 128) sidx[tid] = g_idx[pix0 + tid];
    __syncthreads();

    float lsum = 0.f;
#pragma unroll 4
    for (int it = 0; it < (128 * EMB_DIM) / 256; it++) {
        int i = tid + it * 256;
        int p = i & 127;
        int c = i >> 7;
        int idx = sidx[p];
        float q = __ldg(&emb[(size_t)idx * EMB_DIM + c]);
        float xv = xbase[(size_t)c * HW + p];
        out[1 + ((size_t)b * EMB_DIM + c) * HW + hw0 + p] = q;
        float d = q - xv;
        lsum = fmaf(d, d, lsum);
    }
#pragma unroll
    for (int off = 16; off > 0; off >>= 1)
        lsum += __shfl_down_sync(0xffffffffu, lsum, off);
    if ((tid & 31) == 0) s_loss[tid >> 5] = (double)lsum;
    __syncthreads();
    if (tid == 0) {
        double tt = 0.0;
#pragma unroll
        for (int w = 0; w < 8; w++) tt += s_loss[w];
        atomicAdd(&g_loss, tt);
    }
}

__global__ void vq_finalize_kernel(float* __restrict__ out) {
    out[0] = (float)(g_loss * (1.0625 / 16777216.0));
}

extern "C" void kernel_launch(void* const* d_in, const int* in_sizes, int n_in,
                              void* d_out, int out_size) {
    const float* x = (const float*)d_in[0];
    const float* emb = (const float*)d_in[1];
    float* out = (float*)d_out;

    cudaFuncSetAttribute(vq_gemm_kernel,
                         cudaFuncAttributeMaxDynamicSharedMemorySize, GEMM_DSMEM);

    vq_esplit_kernel<<<NUM_EMB, 256>>>(emb);
    vq_etrans_kernel<<<EMB_DIM, 256>>>(emb);
    vq_enorm_kernel<<<NUM_EMB / 32, 256>>>(emb);
    vq_xsplit_kernel<<<NPIX / 128, 256>>>(x);
    vq_gemm_kernel<<<NPIX / 128, 256, GEMM_DSMEM>>>();
    vq_rescue_kernel<<<148, 256>>>(x);
    vq_writeback_kernel<<<NPIX / 128, 256>>>(x, emb, out);
    vq_finalize_kernel<<<1, 1>>>(out);
}

// round 15
// speedup vs baseline: 4.6461x; 1.0490x over previous
#include <cuda_runtime.h>
#include <cuda_bf16.h>
#include <cstdint>

// VQ-VAE quantizer: bf16-split HMMA screening (K'=512: hi_x·[hi_e|lo_e],
// flattened 3-stage cp.async pipeline, ldmatrix fragments) + exact-chain
// rescue, reproducing the JAX/XLA-CPU fp32 reference argmin bitwise.
//   x: [16, 256, 64, 64] f32   (d_in[0])
//   emb: [1024, 256] f32       (d_in[1])
//   out: [1 + 16*256*64*64] f32: out[0]=c_loss, out[1:]=quant_out (NCHW)

#define NUM_EMB 1024
#define EMB_DIM 256
#define HW 4096
#define NPIX 65536
#define KE 512                  // E split columns: [hi | lo]
#define MARGIN 3.0e-4f
#define STAGE_B 18432           // 128 rows x 72 halves x 2B
#define GEMM_DSMEM (6 * STAGE_B)   // 3 stages A + 3 stages B = 108 KB
#define RESC_PIX 16

__device__ double g_loss;
__device__ float g_enorm[NUM_EMB];
__device__ float g_xnorm[NPIX];
__device__ int g_idx[NPIX];
__device__ int g_resc_count;
__device__ int g_resc[NPIX];
__device__ __nv_bfloat16 g_Xp[(size_t)NPIX * EMB_DIM];  // [pixel][256] hi only
__device__ __nv_bfloat16 g_Ep[NUM_EMB * KE];            // [code][512] hi|lo
__device__ float g_EpT[EMB_DIM * NUM_EMB];              // [c][k] transposed emb

#define MMA16816(d, a0, a1, a2, a3, bb0, bb1) \
    asm volatile("mma.sync.aligned.m16n8k16.row.col.f32.bf16.bf16.f32 " \
                 "{%0,%1,%2,%3}, {%4,%5,%6,%7}, {%8,%9}, {%0,%1,%2,%3};" \
                 : "+f"((d)[0]), "+f"((d)[1]), "+f"((d)[2]), "+f"((d)[3]) \
                 : "r"(a0), "r"(a1), "r"(a2), "r"(a3), "r"(bb0), "r"(bb1))
#define LDSM4(r0, r1, r2, r3, addr) \
    asm volatile("ldmatrix.sync.aligned.m8n8.x4.shared.b16 {%0,%1,%2,%3}, [%4];" \
                 : "=r"(r0), "=r"(r1), "=r"(r2), "=r"(r3) : "r"(addr))
#define CPASYNC16(dst_u32, src) \
    asm volatile("cp.async.cg.shared.global [%0], [%1], 16;" \
                 :: "r"(dst_u32), "l"(src) : "memory")
#define CPCOMMIT() asm volatile("cp.async.commit_group;" ::: "memory")
#define CPWAIT1() asm volatile("cp.async.wait_group 1;" ::: "memory")
#define CPWAIT0() asm volatile("cp.async.wait_group 0;" ::: "memory")

__device__ __forceinline__ uint32_t smem_u32(const void* p) {
    uint32_t a;
    asm("{ .reg .u64 t; cvta.to.shared.u64 t, %1; cvt.u32.u64 %0, t; }" : "=r"(a) : "l"(p));
    return a;
}

// ---------------- kernel 1a: coalesced E split (+ zero accumulators) --------
__global__ void vq_esplit_kernel(const float* __restrict__ emb) {
    const int k = blockIdx.x;       // 1024 blocks
    const int c = threadIdx.x;      // 256 threads
    if (k == 0 && c == 0) { g_loss = 0.0; g_resc_count = 0; }
    float v = emb[(size_t)k * EMB_DIM + c];
    __nv_bfloat16 hi = __float2bfloat16_rn(v);
    __nv_bfloat16 lo = __float2bfloat16_rn(v - __bfloat162float(hi));
    __nv_bfloat16* er = g_Ep + (size_t)k * KE;
    er[c] = hi; er[256 + c] = lo;
}

// ---------------- kernel 1b: transpose emb -> g_EpT[c][k] -------------------
__global__ void vq_etrans_kernel(const float* __restrict__ emb) {
    const int c = blockIdx.x;       // 256 blocks
#pragma unroll
    for (int q = 0; q < 4; q++) {
        int k = threadIdx.x + q * 256;
        g_EpT[c * NUM_EMB + k] = emb[(size_t)k * EMB_DIM + c];
    }
}

// ---------------- kernel 1c: ||e_k||^2, 8 lanes/code, exact XLA tree --------
__global__ void vq_enorm_kernel(const float* __restrict__ emb) {
    const int tid = threadIdx.x;
    const int gw = (blockIdx.x * blockDim.x + tid) >> 5;
    const int lane = tid & 31;
    const int k = gw * 4 + (lane >> 3);
    const int r = lane & 7;
    const float* row = emb + (size_t)k * EMB_DIM;
    float S = 0.f;
#pragma unroll 8
    for (int j = 0; j < 32; j++) {
        float v = row[r + 8 * j];
        S = __fadd_rn(S, __fmul_rn(v, v));
    }
    float o = __shfl_down_sync(0xffffffffu, S, 4, 8);
    float T = __fadd_rn(S, o);
    o = __shfl_down_sync(0xffffffffu, T, 2, 8);
    float U = __fadd_rn(T, o);
    o = __shfl_down_sync(0xffffffffu, U, 1, 8);
    float R = __fadd_rn(U, o);
    if (r == 0) g_enorm[k] = R;
}

// ---------------- kernel 2: split X (hi only) + fused ||x||^2 --------------
__global__ __launch_bounds__(256)
void vq_xsplit_kernel(const float* __restrict__ x) {
    __shared__ float xs[128 * 66];   // [p][c], stride 66
    const int tid = threadIdx.x;
    const int pix0 = blockIdx.x * 128;
    const int b = pix0 >> 12;
    const int hw0 = pix0 & (HW - 1);
    const float* xbase = x + ((size_t)b * EMB_DIM) * HW + hw0;
    const int r = tid & 7;

    float S4[4];
#pragma unroll
    for (int sl = 0; sl < 4; sl++) S4[sl] = 0.f;

    for (int c0 = 0; c0 < EMB_DIM; c0 += 64) {
        __syncthreads();
#pragma unroll
        for (int it = 0; it < 32; it++) {
            int i = tid + it * 256;
            int p = i & 127, c = i >> 7;
            xs[p * 66 + c] = xbase[(size_t)(c0 + c) * HW + p];
        }
        __syncthreads();
#pragma unroll
        for (int it = 0; it < 16; it++) {
            int i = tid + it * 256;
            int p = i >> 5, cp = i & 31;
            float2 v = *(const float2*)&xs[p * 66 + 2 * cp];
            __nv_bfloat162 hh;
            hh.x = __float2bfloat16_rn(v.x);
            hh.y = __float2bfloat16_rn(v.y);
            *(__nv_bfloat162*)&g_Xp[(size_t)(pix0 + p) * EMB_DIM + c0 + 2 * cp] = hh;
        }
        // fused norm accumulation: thread owns (p = tid>>3 + 32*sl, r = tid&7)
#pragma unroll
        for (int sl = 0; sl < 4; sl++) {
            int p = (tid >> 3) + 32 * sl;
            const float* row = &xs[p * 66];
#pragma unroll
            for (int j = 0; j < 8; j++) {
                float v = row[r + 8 * j];
                S4[sl] = __fadd_rn(S4[sl], __fmul_rn(v, v));
            }
        }
    }
#pragma unroll
    for (int sl = 0; sl < 4; sl++) {
        float S = S4[sl];
        float o = __shfl_down_sync(0xffffffffu, S, 4, 8);
        float T = __fadd_rn(S, o);
        o = __shfl_down_sync(0xffffffffu, T, 2, 8);
        float U = __fadd_rn(T, o);
        o = __shfl_down_sync(0xffffffffu, U, 1, 8);
        float R = __fadd_rn(U, o);
        if (r == 0) g_xnorm[pix0 + (tid >> 3) + 32 * sl] = R;
    }
}

// ---------------- kernel 4: HMMA GEMM screening + argmin -------------------
// Flattened 64-chunk mainloop (8 tiles x 8 kc), 3 smem stages, ONE barrier
// per chunk. A chunk source: hi array col (kc&3)*64 (read twice per tile);
// B chunk source: [hi|lo] col kc*64.
__global__ __launch_bounds__(256, 2)
void vq_gemm_kernel() {
    extern __shared__ __align__(16) char dsm[];
    __nv_bfloat16* As = (__nv_bfloat16*)dsm;                    // 3 stages
    __nv_bfloat16* Bs = (__nv_bfloat16*)(dsm + 3 * STAGE_B);    // 3 stages
    __shared__ float mb1[128];
    __shared__ float mb2[128];
    __shared__ int mi1s[128];

    const int tid = threadIdx.x;
    const int lane = tid & 31;
    const int wid = tid >> 5;
    const int wm = wid & 3;
    const int wn = wid >> 2;
    const int g = lane >> 2;
    const int t = lane & 3;
    const int pix0 = blockIdx.x * 128;

    const uint32_t sA = smem_u32(As);
    const uint32_t sB = smem_u32(Bs);
    const char* XpB = (const char*)g_Xp;
    const char* EpB = (const char*)g_Ep;

    const int lh = lane & 7;
    const int l8 = (lane >> 3) & 1;
    const int l16 = (lane >> 4) & 1;
    const uint32_t aoff = (uint32_t)((32 * wm + lh + 8 * l8) * 144 + l16 * 16);
    const uint32_t boff = (uint32_t)((64 * wn + lh + 8 * l16) * 144 + l8 * 16);

    int frow[4], fcj[4];
#pragma unroll
    for (int it = 0; it < 4; it++) {
        int id = tid + it * 256;
        frow[it] = id >> 3;
        fcj[it] = id & 7;
    }

    float a_p[4];
    int rowOf[4];
#pragma unroll
    for (int s = 0; s < 4; s++) {
        rowOf[s] = 32 * wm + 16 * (s >> 1) + 8 * (s & 1) + g;
        a_p[s] = g_xnorm[pix0 + rowOf[s]];
    }
    float b1[4], b2[4];
    int i1[4];
#pragma unroll
    for (int s = 0; s < 4; s++) { b1[s] = 3.4e38f; b2[s] = 3.4e38f; i1[s] = 0; }

    float acc[2][8][4];

    // prologue: prefetch chunks 0, 1
#pragma unroll
    for (int m = 0; m < 2; m++) {
        const int kc2 = m;  // tile 0
#pragma unroll
        for (int it = 0; it < 4; it++) {
            uint32_t doff = (uint32_t)(m * STAGE_B + frow[it] * 144 + fcj[it] * 16);
            size_t koffA = (size_t)(kc2 & 3) * 64 + fcj[it] * 8;
            size_t koffB = (size_t)kc2 * 64 + fcj[it] * 8;
            CPASYNC16(sA + doff, XpB + ((size_t)(pix0 + frow[it]) * EMB_DIM + koffA) * 2);
            CPASYNC16(sB + doff, EpB + ((size_t)frow[it] * KE + koffB) * 2);
        }
        CPCOMMIT();
    }

    for (int m = 0; m < 64; m++) {
        const int kc = m & 7;
        const uint32_t stB = (uint32_t)((m % 3) * STAGE_B);

        if (kc == 0) {
#pragma unroll
            for (int mi = 0; mi < 2; mi++)
#pragma unroll
                for (int ni = 0; ni < 8; ni++)
#pragma unroll
                    for (int q = 0; q < 4; q++) acc[mi][ni][q] = 0.f;
        }

        if (m == 63) { CPWAIT0(); } else { CPWAIT1(); }
        __syncthreads();

        // compute chunk m from stage m%3
#pragma unroll
        for (int kf = 0; kf < 4; kf++) {
            uint32_t a[2][4];
#pragma unroll
            for (int mi = 0; mi < 2; mi++)
                LDSM4(a[mi][0], a[mi][1], a[mi][2], a[mi][3],
                      sA + stB + aoff + (uint32_t)(mi * 2304 + kf * 32));
#pragma unroll
            for (int np = 0; np < 4; np++) {
                uint32_t bb0, bb1, bb2, bb3;
                LDSM4(bb0, bb1, bb2, bb3,
                      sB + stB + boff + (uint32_t)(np * 2304 + kf * 32));
#pragma unroll
                for (int mi = 0; mi < 2; mi++) {
                    MMA16816(acc[mi][2 * np], a[mi][0], a[mi][1], a[mi][2], a[mi][3], bb0, bb1);
                    MMA16816(acc[mi][2 * np + 1], a[mi][0], a[mi][1], a[mi][2], a[mi][3], bb2, bb3);
                }
            }
        }

        // prefetch chunk m+2 into stage (m+2)%3
        if (m + 2 < 64) {
            const int m2 = m + 2;
            const int tile2 = m2 >> 3, kc2 = m2 & 7;
            const uint32_t st2 = (uint32_t)((m2 % 3) * STAGE_B);
#pragma unroll
            for (int it = 0; it < 4; it++) {
                uint32_t doff = st2 + (uint32_t)(frow[it] * 144 + fcj[it] * 16);
                size_t koffA = (size_t)(kc2 & 3) * 64 + fcj[it] * 8;
                size_t koffB = (size_t)kc2 * 64 + fcj[it] * 8;
                CPASYNC16(sA + doff, XpB + ((size_t)(pix0 + frow[it]) * EMB_DIM + koffA) * 2);
                CPASYNC16(sB + doff, EpB + ((size_t)(tile2 * 128 + frow[it]) * KE + koffB) * 2);
            }
            CPCOMMIT();
        }

        if (kc == 7) {
            // Epilogue for this tile: reference-rounded scores.
            // c-frag: q0=(g,2t) q1=(g,2t+1) q2=(g+8,2t) q3=(g+8,2t+1); s=2mi+(q>>1).
            const int n0 = (m >> 3) * 128;
#pragma unroll
            for (int ni = 0; ni < 8; ni++) {
                int kb = n0 + 64 * wn + 8 * ni + 2 * t;
                float c0 = __ldg(&g_enorm[kb]);
                float c1 = __ldg(&g_enorm[kb + 1]);
#pragma unroll
                for (int mi = 0; mi < 2; mi++) {
#pragma unroll
                    for (int q = 0; q < 4; q++) {
                        int s = 2 * mi + (q >> 1);
                        float bv = acc[mi][ni][q];
                        int k = kb + (q & 1);
                        float cn = (q & 1) ? c1 : c0;
                        float sc = __fadd_rn(__fsub_rn(a_p[s], __fmul_rn(2.0f, bv)), cn);
                        if (sc < b1[s]) { b2[s] = b1[s]; b1[s] = sc; i1[s] = k; }
                        else if (sc < b2[s]) { b2[s] = sc; }
                    }
                }
            }
        }
    }

#pragma unroll
    for (int s = 0; s < 4; s++) {
        float x1 = b1[s], x2 = b2[s];
        int xi = i1[s];
#pragma unroll
        for (int off = 2; off > 0; off >>= 1) {
            float o1 = __shfl_down_sync(0xffffffffu, x1, off, 4);
            float o2 = __shfl_down_sync(0xffffffffu, x2, off, 4);
            int oi = __shfl_down_sync(0xffffffffu, xi, off, 4);
            float n2 = fminf(fmaxf(x1, o1), fminf(x2, o2));
            if (o1 < x1 || (o1 == x1 && oi < xi)) { x1 = o1; xi = oi; }
            x2 = n2;
        }
        b1[s] = x1; b2[s] = x2; i1[s] = xi;
    }
    if (wn == 0 && t == 0) {
#pragma unroll
        for (int s = 0; s < 4; s++) {
            mb1[rowOf[s]] = b1[s];
            mb2[rowOf[s]] = b2[s];
            mi1s[rowOf[s]] = i1[s];
        }
    }
    __syncthreads();
    if (wn == 1 && t == 0) {
#pragma unroll
        for (int s = 0; s < 4; s++) {
            int r = rowOf[s];
            float o1 = mb1[r], o2 = mb2[r];
            int oi = mi1s[r];
            float n2 = fminf(fmaxf(b1[s], o1), fminf(b2[s], o2));
            float n1;
            int ni_;
            if (o1 < b1[s] || (o1 == b1[s] && oi < i1[s])) { n1 = o1; ni_ = oi; }
            else { n1 = b1[s]; ni_ = i1[s]; }
            int p = pix0 + r;
            g_idx[p] = ni_;
            if (n2 - n1 < MARGIN) {
                int rr = atomicAdd(&g_resc_count, 1);
                g_resc[rr] = p;
            }
        }
    }
}

// ---------------- kernel 5: exact rescue, 16 pixels/block, coalesced -------
__global__ __launch_bounds__(256)
void vq_rescue_kernel(const float* __restrict__ x) {
    __shared__ float xsm[RESC_PIX * 256];
    __shared__ int plist[RESC_PIX];
    __shared__ float rbs[RESC_PIX * 8];
    __shared__ int rbk[RESC_PIX * 8];
    const int tid = threadIdx.x;
    const int lane = tid & 31, wid = tid >> 5;
    const int cnt = g_resc_count;

    for (int base = blockIdx.x * RESC_PIX; base < cnt; base += gridDim.x * RESC_PIX) {
        const int nv = min(RESC_PIX, cnt - base);
        __syncthreads();
        if (tid < RESC_PIX)
            plist[tid] = g_resc[base + ((tid < nv) ? tid : 0)];
        __syncthreads();
        for (int j = wid; j < RESC_PIX; j += 8) {
            int p = plist[j];
            int b = p >> 12, hw = p & (HW - 1);
            const float* xb = x + ((size_t)b * EMB_DIM) * HW + hw;
            for (int c = lane; c < EMB_DIM; c += 32)
                xsm[j * 256 + c] = xb[(size_t)c * HW];
        }
        __syncthreads();

        float best[RESC_PIX];
        int bidx[RESC_PIX];
#pragma unroll
        for (int j = 0; j < RESC_PIX; j++) { best[j] = 3.4e38f; bidx[j] = 0; }

#pragma unroll
        for (int pass = 0; pass < 2; pass++) {
            const int k0 = tid + (2 * pass) * 256;
            const int k1 = tid + (2 * pass + 1) * 256;
            float acc0[RESC_PIX], acc1[RESC_PIX];
#pragma unroll
            for (int j = 0; j < RESC_PIX; j++) { acc0[j] = 0.f; acc1[j] = 0.f; }
            for (int c = 0; c < EMB_DIM; c++) {
                float e0 = g_EpT[c * NUM_EMB + k0];
                float e1 = g_EpT[c * NUM_EMB + k1];
#pragma unroll
                for (int j = 0; j < RESC_PIX; j++) {
                    float xv = xsm[j * 256 + c];
                    acc0[j] = fmaf(xv, e0, acc0[j]);
                    acc1[j] = fmaf(xv, e1, acc1[j]);
                }
            }
            float en0 = g_enorm[k0], en1 = g_enorm[k1];
#pragma unroll
            for (int j = 0; j < RESC_PIX; j++) {
                float a = g_xnorm[plist[j]];
                float s0 = __fadd_rn(__fsub_rn(a, __fmul_rn(2.0f, acc0[j])), en0);
                float s1 = __fadd_rn(__fsub_rn(a, __fmul_rn(2.0f, acc1[j])), en1);
                if (s0 < best[j]) { best[j] = s0; bidx[j] = k0; }
                if (s1 < best[j]) { best[j] = s1; bidx[j] = k1; }
            }
        }
#pragma unroll
        for (int j = 0; j < RESC_PIX; j++) {
            float s = best[j];
            int k = bidx[j];
#pragma unroll
            for (int off = 16; off > 0; off >>= 1) {
                float so = __shfl_down_sync(0xffffffffu, s, off);
                int ko = __shfl_down_sync(0xffffffffu, k, off);
                if (so < s || (so == s && ko < k)) { s = so; k = ko; }
            }
            if (lane == 0) { rbs[j * 8 + wid] = s; rbk[j * 8 + wid] = k; }
        }
        __syncthreads();
        if (tid < nv) {
            float s = rbs[tid * 8];
            int k = rbk[tid * 8];
#pragma unroll
            for (int w = 1; w < 8; w++) {
                float so = rbs[tid * 8 + w];
                int ko = rbk[tid * 8 + w];
                if (so < s || (so == s && ko < k)) { s = so; k = ko; }
            }
            g_idx[plist[tid]] = k;
        }
    }
}

// ---------------- kernel 6: gather/writeback + loss ----------------
__global__ __launch_bounds__(256)
void vq_writeback_kernel(const float* __restrict__ x,
                         const float* __restrict__ emb,
                         float* __restrict__ out) {
    __shared__ int sidx[128];
    __shared__ double s_loss[8];
    const int tid = threadIdx.x;
    const int pix0 = blockIdx.x * 128;
    const int b = pix0 >> 12;
    const int hw0 = pix0 & (HW - 1);
    const float* xbase = x + ((size_t)b * EMB_DIM) * HW + hw0;

    if (tid < 128) sidx[tid] = g_idx[pix0 + tid];
    __syncthreads();

    float lsum = 0.f;
#pragma unroll 4
    for (int it = 0; it < (128 * EMB_DIM) / 256; it++) {
        int i = tid + it * 256;
        int p = i & 127;
        int c = i >> 7;
        int idx = sidx[p];
        float q = __ldg(&emb[(size_t)idx * EMB_DIM + c]);
        float xv = xbase[(size_t)c * HW + p];
        out[1 + ((size_t)b * EMB_DIM + c) * HW + hw0 + p] = q;
        float d = q - xv;
        lsum = fmaf(d, d, lsum);
    }
#pragma unroll
    for (int off = 16; off > 0; off >>= 1)
        lsum += __shfl_down_sync(0xffffffffu, lsum, off);
    if ((tid & 31) == 0) s_loss[tid >> 5] = (double)lsum;
    __syncthreads();
    if (tid == 0) {
        double tt = 0.0;
#pragma unroll
        for (int w = 0; w < 8; w++) tt += s_loss[w];
        atomicAdd(&g_loss, tt);
    }
}

__global__ void vq_finalize_kernel(float* __restrict__ out) {
    out[0] = (float)(g_loss * (1.0625 / 16777216.0));
}

extern "C" void kernel_launch(void* const* d_in, const int* in_sizes, int n_in,
                              void* d_out, int out_size) {
    const float* x = (const float*)d_in[0];
    const float* emb = (const float*)d_in[1];
    float* out = (float*)d_out;

    cudaFuncSetAttribute(vq_gemm_kernel,
                         cudaFuncAttributeMaxDynamicSharedMemorySize, GEMM_DSMEM);

    vq_esplit_kernel<<<NUM_EMB, 256>>>(emb);
    vq_etrans_kernel<<<EMB_DIM, 256>>>(emb);
    vq_enorm_kernel<<<NUM_EMB / 32, 256>>>(emb);
    vq_xsplit_kernel<<<NPIX / 128, 256>>>(x);
    vq_gemm_kernel<<<NPIX / 128, 256, GEMM_DSMEM>>>();
    vq_rescue_kernel<<<148, 256>>>(x);
    vq_writeback_kernel<<<NPIX / 128, 256>>>(x, emb, out);
    vq_finalize_kernel<<<1, 1>>>(out);
}

// round 16
// speedup vs baseline: 5.7726x; 1.2425x over previous
#include <cuda_runtime.h>
#include <cuda_bf16.h>
#include <cstdint>

// VQ-VAE quantizer: bf16 hi-only HMMA screening (K'=256, flattened 3-stage
// cp.async pipeline, ldmatrix fragments, fused loss) + exact-chain rescue,
// reproducing the JAX/XLA-CPU fp32 reference argmin bitwise.
//   x: [16, 256, 64, 64] f32   (d_in[0])
//   emb: [1024, 256] f32       (d_in[1])
//   out: [1 + 16*256*64*64] f32: out[0]=c_loss, out[1:]=quant_out (NCHW)

#define NUM_EMB 1024
#define EMB_DIM 256
#define HW 4096
#define NPIX 65536
#define MARGIN 3.0e-4f
#define STAGE_B 18432           // 128 rows x 72 halves x 2B
#define GEMM_DSMEM (6 * STAGE_B)   // 3 stages A + 3 stages B = 108 KB
#define RESC_PIX 16

__device__ double g_loss;
__device__ float g_enorm[NUM_EMB];
__device__ float g_xnorm[NPIX];
__device__ int g_idx[NPIX];
__device__ int g_resc_count;
__device__ int g_resc[NPIX];
__device__ __nv_bfloat16 g_Xp[(size_t)NPIX * EMB_DIM];  // [pixel][256] hi(x)
__device__ __nv_bfloat16 g_Ep[NUM_EMB * EMB_DIM];       // [code][256] hi(e)
__device__ float g_EpT[EMB_DIM * NUM_EMB];              // [c][k] transposed emb

#define MMA16816(d, a0, a1, a2, a3, bb0, bb1) \
    asm volatile("mma.sync.aligned.m16n8k16.row.col.f32.bf16.bf16.f32 " \
                 "{%0,%1,%2,%3}, {%4,%5,%6,%7}, {%8,%9}, {%0,%1,%2,%3};" \
                 : "+f"((d)[0]), "+f"((d)[1]), "+f"((d)[2]), "+f"((d)[3]) \
                 : "r"(a0), "r"(a1), "r"(a2), "r"(a3), "r"(bb0), "r"(bb1))
#define LDSM4(r0, r1, r2, r3, addr) \
    asm volatile("ldmatrix.sync.aligned.m8n8.x4.shared.b16 {%0,%1,%2,%3}, [%4];" \
                 : "=r"(r0), "=r"(r1), "=r"(r2), "=r"(r3) : "r"(addr))
#define CPASYNC16(dst_u32, src) \
    asm volatile("cp.async.cg.shared.global [%0], [%1], 16;" \
                 :: "r"(dst_u32), "l"(src) : "memory")
#define CPCOMMIT() asm volatile("cp.async.commit_group;" ::: "memory")
#define CPWAIT1() asm volatile("cp.async.wait_group 1;" ::: "memory")
#define CPWAIT0() asm volatile("cp.async.wait_group 0;" ::: "memory")

__device__ __forceinline__ uint32_t smem_u32(const void* p) {
    uint32_t a;
    asm("{ .reg .u64 t; cvta.to.shared.u64 t, %1; cvt.u32.u64 %0, t; }" : "=r"(a) : "l"(p));
    return a;
}

// ---------------- kernel 1a: coalesced E split (+ zero accumulators) --------
__global__ void vq_esplit_kernel(const float* __restrict__ emb) {
    const int k = blockIdx.x;       // 1024 blocks
    const int c = threadIdx.x;      // 256 threads
    if (k == 0 && c == 0) { g_loss = 0.0; g_resc_count = 0; }
    float v = emb[(size_t)k * EMB_DIM + c];
    g_Ep[(size_t)k * EMB_DIM + c] = __float2bfloat16_rn(v);
}

// ---------------- kernel 1b: transpose emb -> g_EpT[c][k] -------------------
__global__ void vq_etrans_kernel(const float* __restrict__ emb) {
    const int c = blockIdx.x;       // 256 blocks
#pragma unroll
    for (int q = 0; q < 4; q++) {
        int k = threadIdx.x + q * 256;
        g_EpT[c * NUM_EMB + k] = emb[(size_t)k * EMB_DIM + c];
    }
}

// ---------------- kernel 1c: ||e_k||^2, 8 lanes/code, exact XLA tree --------
__global__ void vq_enorm_kernel(const float* __restrict__ emb) {
    const int tid = threadIdx.x;
    const int gw = (blockIdx.x * blockDim.x + tid) >> 5;
    const int lane = tid & 31;
    const int k = gw * 4 + (lane >> 3);
    const int r = lane & 7;
    const float* row = emb + (size_t)k * EMB_DIM;
    float S = 0.f;
#pragma unroll 8
    for (int j = 0; j < 32; j++) {
        float v = row[r + 8 * j];
        S = __fadd_rn(S, __fmul_rn(v, v));
    }
    float o = __shfl_down_sync(0xffffffffu, S, 4, 8);
    float T = __fadd_rn(S, o);
    o = __shfl_down_sync(0xffffffffu, T, 2, 8);
    float U = __fadd_rn(T, o);
    o = __shfl_down_sync(0xffffffffu, U, 1, 8);
    float R = __fadd_rn(U, o);
    if (r == 0) g_enorm[k] = R;
}

// ---------------- kernel 2: split X (hi only) + fused ||x||^2 --------------
__global__ __launch_bounds__(256)
void vq_xsplit_kernel(const float* __restrict__ x) {
    __shared__ float xs[128 * 66];   // [p][c], stride 66
    const int tid = threadIdx.x;
    const int pix0 = blockIdx.x * 128;
    const int b = pix0 >> 12;
    const int hw0 = pix0 & (HW - 1);
    const float* xbase = x + ((size_t)b * EMB_DIM) * HW + hw0;
    const int r = tid & 7;

    float S4[4];
#pragma unroll
    for (int sl = 0; sl < 4; sl++) S4[sl] = 0.f;

    for (int c0 = 0; c0 < EMB_DIM; c0 += 64) {
        __syncthreads();
#pragma unroll
        for (int it = 0; it < 32; it++) {
            int i = tid + it * 256;
            int p = i & 127, c = i >> 7;
            xs[p * 66 + c] = xbase[(size_t)(c0 + c) * HW + p];
        }
        __syncthreads();
#pragma unroll
        for (int it = 0; it < 16; it++) {
            int i = tid + it * 256;
            int p = i >> 5, cp = i & 31;
            float2 v = *(const float2*)&xs[p * 66 + 2 * cp];
            __nv_bfloat162 hh;
            hh.x = __float2bfloat16_rn(v.x);
            hh.y = __float2bfloat16_rn(v.y);
            *(__nv_bfloat162*)&g_Xp[(size_t)(pix0 + p) * EMB_DIM + c0 + 2 * cp] = hh;
        }
#pragma unroll
        for (int sl = 0; sl < 4; sl++) {
            int p = (tid >> 3) + 32 * sl;
            const float* row = &xs[p * 66];
#pragma unroll
            for (int j = 0; j < 8; j++) {
                float v = row[r + 8 * j];
                S4[sl] = __fadd_rn(S4[sl], __fmul_rn(v, v));
            }
        }
    }
#pragma unroll
    for (int sl = 0; sl < 4; sl++) {
        float S = S4[sl];
        float o = __shfl_down_sync(0xffffffffu, S, 4, 8);
        float T = __fadd_rn(S, o);
        o = __shfl_down_sync(0xffffffffu, T, 2, 8);
        float U = __fadd_rn(T, o);
        o = __shfl_down_sync(0xffffffffu, U, 1, 8);
        float R = __fadd_rn(U, o);
        if (r == 0) g_xnorm[pix0 + (tid >> 3) + 32 * sl] = R;
    }
}

// ---------------- kernel 4: HMMA GEMM screening + argmin + fused loss ------
// Flattened 32-chunk mainloop (8 tiles x 4 kc), 3 smem stages, ONE barrier
// per chunk. score = ||x-q||^2 so sum of best scores = MSE numerator.
__global__ __launch_bounds__(256, 2)
void vq_gemm_kernel() {
    extern __shared__ __align__(16) char dsm[];
    __nv_bfloat16* As = (__nv_bfloat16*)dsm;                    // 3 stages
    __nv_bfloat16* Bs = (__nv_bfloat16*)(dsm + 3 * STAGE_B);    // 3 stages
    __shared__ float mb1[128];
    __shared__ float mb2[128];
    __shared__ int mi1s[128];
    __shared__ float s_lsum;

    const int tid = threadIdx.x;
    const int lane = tid & 31;
    const int wid = tid >> 5;
    const int wm = wid & 3;
    const int wn = wid >> 2;
    const int g = lane >> 2;
    const int t = lane & 3;
    const int pix0 = blockIdx.x * 128;

    if (tid == 0) s_lsum = 0.f;

    const uint32_t sA = smem_u32(As);
    const uint32_t sB = smem_u32(Bs);
    const char* XpB = (const char*)g_Xp;
    const char* EpB = (const char*)g_Ep;

    const int lh = lane & 7;
    const int l8 = (lane >> 3) & 1;
    const int l16 = (lane >> 4) & 1;
    const uint32_t aoff = (uint32_t)((32 * wm + lh + 8 * l8) * 144 + l16 * 16);
    const uint32_t boff = (uint32_t)((64 * wn + lh + 8 * l16) * 144 + l8 * 16);

    int frow[4], fcj[4];
#pragma unroll
    for (int it = 0; it < 4; it++) {
        int id = tid + it * 256;
        frow[it] = id >> 3;
        fcj[it] = id & 7;
    }

    float a_p[4];
    int rowOf[4];
#pragma unroll
    for (int s = 0; s < 4; s++) {
        rowOf[s] = 32 * wm + 16 * (s >> 1) + 8 * (s & 1) + g;
        a_p[s] = g_xnorm[pix0 + rowOf[s]];
    }
    float b1[4], b2[4];
    int i1[4];
#pragma unroll
    for (int s = 0; s < 4; s++) { b1[s] = 3.4e38f; b2[s] = 3.4e38f; i1[s] = 0; }

    float acc[2][8][4];

    // prologue: prefetch chunks 0, 1 (tile 0, kc 0/1)
#pragma unroll
    for (int m = 0; m < 2; m++) {
#pragma unroll
        for (int it = 0; it < 4; it++) {
            uint32_t doff = (uint32_t)(m * STAGE_B + frow[it] * 144 + fcj[it] * 16);
            size_t koff = (size_t)m * 64 + fcj[it] * 8;
            CPASYNC16(sA + doff, XpB + ((size_t)(pix0 + frow[it]) * EMB_DIM + koff) * 2);
            CPASYNC16(sB + doff, EpB + ((size_t)frow[it] * EMB_DIM + koff) * 2);
        }
        CPCOMMIT();
    }

    for (int m = 0; m < 32; m++) {
        const int kc = m & 3;
        const uint32_t stB = (uint32_t)((m % 3) * STAGE_B);

        if (kc == 0) {
#pragma unroll
            for (int mi = 0; mi < 2; mi++)
#pragma unroll
                for (int ni = 0; ni < 8; ni++)
#pragma unroll
                    for (int q = 0; q < 4; q++) acc[mi][ni][q] = 0.f;
        }

        if (m == 31) { CPWAIT0(); } else { CPWAIT1(); }
        __syncthreads();

        // compute chunk m from stage m%3
#pragma unroll
        for (int kf = 0; kf < 4; kf++) {
            uint32_t a[2][4];
#pragma unroll
            for (int mi = 0; mi < 2; mi++)
                LDSM4(a[mi][0], a[mi][1], a[mi][2], a[mi][3],
                      sA + stB + aoff + (uint32_t)(mi * 2304 + kf * 32));
#pragma unroll
            for (int np = 0; np < 4; np++) {
                uint32_t bb0, bb1, bb2, bb3;
                LDSM4(bb0, bb1, bb2, bb3,
                      sB + stB + boff + (uint32_t)(np * 2304 + kf * 32));
#pragma unroll
                for (int mi = 0; mi < 2; mi++) {
                    MMA16816(acc[mi][2 * np], a[mi][0], a[mi][1], a[mi][2], a[mi][3], bb0, bb1);
                    MMA16816(acc[mi][2 * np + 1], a[mi][0], a[mi][1], a[mi][2], a[mi][3], bb2, bb3);
                }
            }
        }

        // prefetch chunk m+2 into stage (m+2)%3
        if (m + 2 < 32) {
            const int m2 = m + 2;
            const int tile2 = m2 >> 2, kc2 = m2 & 3;
            const uint32_t st2 = (uint32_t)((m2 % 3) * STAGE_B);
#pragma unroll
            for (int it = 0; it < 4; it++) {
                uint32_t doff = st2 + (uint32_t)(frow[it] * 144 + fcj[it] * 16);
                size_t koff = (size_t)kc2 * 64 + fcj[it] * 8;
                CPASYNC16(sA + doff, XpB + ((size_t)(pix0 + frow[it]) * EMB_DIM + koff) * 2);
                CPASYNC16(sB + doff, EpB + ((size_t)(tile2 * 128 + frow[it]) * EMB_DIM + koff) * 2);
            }
            CPCOMMIT();
        }

        if (kc == 3) {
            // Epilogue for this tile: reference-rounded scores.
            // c-frag: q0=(g,2t) q1=(g,2t+1) q2=(g+8,2t) q3=(g+8,2t+1); s=2mi+(q>>1).
            const int n0 = (m >> 2) * 128;
#pragma unroll
            for (int ni = 0; ni < 8; ni++) {
                int kb = n0 + 64 * wn + 8 * ni + 2 * t;
                float c0 = __ldg(&g_enorm[kb]);
                float c1 = __ldg(&g_enorm[kb + 1]);
#pragma unroll
                for (int mi = 0; mi < 2; mi++) {
#pragma unroll
                    for (int q = 0; q < 4; q++) {
                        int s = 2 * mi + (q >> 1);
                        float bv = acc[mi][ni][q];
                        int k = kb + (q & 1);
                        float cn = (q & 1) ? c1 : c0;
                        float sc = __fadd_rn(__fsub_rn(a_p[s], __fmul_rn(2.0f, bv)), cn);
                        if (sc < b1[s]) { b2[s] = b1[s]; b1[s] = sc; i1[s] = k; }
                        else if (sc < b2[s]) { b2[s] = sc; }
                    }
                }
            }
        }
    }

#pragma unroll
    for (int s = 0; s < 4; s++) {
        float x1 = b1[s], x2 = b2[s];
        int xi = i1[s];
#pragma unroll
        for (int off = 2; off > 0; off >>= 1) {
            float o1 = __shfl_down_sync(0xffffffffu, x1, off, 4);
            float o2 = __shfl_down_sync(0xffffffffu, x2, off, 4);
            int oi = __shfl_down_sync(0xffffffffu, xi, off, 4);
            float n2 = fminf(fmaxf(x1, o1), fminf(x2, o2));
            if (o1 < x1 || (o1 == x1 && oi < xi)) { x1 = o1; xi = oi; }
            x2 = n2;
        }
        b1[s] = x1; b2[s] = x2; i1[s] = xi;
    }
    if (wn == 0 && t == 0) {
#pragma unroll
        for (int s = 0; s < 4; s++) {
            mb1[rowOf[s]] = b1[s];
            mb2[rowOf[s]] = b2[s];
            mi1s[rowOf[s]] = i1[s];
        }
    }
    __syncthreads();
    if (wn == 1 && t == 0) {
        float ls = 0.f;
#pragma unroll
        for (int s = 0; s < 4; s++) {
            int r = rowOf[s];
            float o1 = mb1[r], o2 = mb2[r];
            int oi = mi1s[r];
            float n2 = fminf(fmaxf(b1[s], o1), fminf(b2[s], o2));
            float n1;
            int ni_;
            if (o1 < b1[s] || (o1 == b1[s] && oi < i1[s])) { n1 = o1; ni_ = oi; }
            else { n1 = b1[s]; ni_ = i1[s]; }
            int p = pix0 + r;
            g_idx[p] = ni_;
            ls += n1;                       // score = ||x - q||^2 (loss term)
            if (n2 - n1 < MARGIN) {
                int rr = atomicAdd(&g_resc_count, 1);
                g_resc[rr] = p;
            }
        }
        atomicAdd(&s_lsum, ls);
    }
    __syncthreads();
    if (tid == 0) atomicAdd(&g_loss, (double)s_lsum);
}

// ---------------- kernel 5: exact rescue, 16 pixels/block, coalesced -------
__global__ __launch_bounds__(256)
void vq_rescue_kernel(const float* __restrict__ x) {
    __shared__ float xsm[RESC_PIX * 256];
    __shared__ int plist[RESC_PIX];
    __shared__ float rbs[RESC_PIX * 8];
    __shared__ int rbk[RESC_PIX * 8];
    const int tid = threadIdx.x;
    const int lane = tid & 31, wid = tid >> 5;
    const int cnt = g_resc_count;

    for (int base = blockIdx.x * RESC_PIX; base < cnt; base += gridDim.x * RESC_PIX) {
        const int nv = min(RESC_PIX, cnt - base);
        __syncthreads();
        if (tid < RESC_PIX)
            plist[tid] = g_resc[base + ((tid < nv) ? tid : 0)];
        __syncthreads();
        for (int j = wid; j < RESC_PIX; j += 8) {
            int p = plist[j];
            int b = p >> 12, hw = p & (HW - 1);
            const float* xb = x + ((size_t)b * EMB_DIM) * HW + hw;
            for (int c = lane; c < EMB_DIM; c += 32)
                xsm[j * 256 + c] = xb[(size_t)c * HW];
        }
        __syncthreads();

        float best[RESC_PIX];
        int bidx[RESC_PIX];
#pragma unroll
        for (int j = 0; j < RESC_PIX; j++) { best[j] = 3.4e38f; bidx[j] = 0; }

#pragma unroll
        for (int pass = 0; pass < 2; pass++) {
            const int k0 = tid + (2 * pass) * 256;
            const int k1 = tid + (2 * pass + 1) * 256;
            float acc0[RESC_PIX], acc1[RESC_PIX];
#pragma unroll
            for (int j = 0; j < RESC_PIX; j++) { acc0[j] = 0.f; acc1[j] = 0.f; }
            for (int c = 0; c < EMB_DIM; c++) {
                float e0 = g_EpT[c * NUM_EMB + k0];
                float e1 = g_EpT[c * NUM_EMB + k1];
#pragma unroll
                for (int j = 0; j < RESC_PIX; j++) {
                    float xv = xsm[j * 256 + c];
                    acc0[j] = fmaf(xv, e0, acc0[j]);
                    acc1[j] = fmaf(xv, e1, acc1[j]);
                }
            }
            float en0 = g_enorm[k0], en1 = g_enorm[k1];
#pragma unroll
            for (int j = 0; j < RESC_PIX; j++) {
                float a = g_xnorm[plist[j]];
                float s0 = __fadd_rn(__fsub_rn(a, __fmul_rn(2.0f, acc0[j])), en0);
                float s1 = __fadd_rn(__fsub_rn(a, __fmul_rn(2.0f, acc1[j])), en1);
                if (s0 < best[j]) { best[j] = s0; bidx[j] = k0; }
                if (s1 < best[j]) { best[j] = s1; bidx[j] = k1; }
            }
        }
#pragma unroll
        for (int j = 0; j < RESC_PIX; j++) {
            float s = best[j];
            int k = bidx[j];
#pragma unroll
            for (int off = 16; off > 0; off >>= 1) {
                float so = __shfl_down_sync(0xffffffffu, s, off);
                int ko = __shfl_down_sync(0xffffffffu, k, off);
                if (so < s || (so == s && ko < k)) { s = so; k = ko; }
            }
            if (lane == 0) { rbs[j * 8 + wid] = s; rbk[j * 8 + wid] = k; }
        }
        __syncthreads();
        if (tid < nv) {
            float s = rbs[tid * 8];
            int k = rbk[tid * 8];
#pragma unroll
            for (int w = 1; w < 8; w++) {
                float so = rbs[tid * 8 + w];
                int ko = rbk[tid * 8 + w];
                if (so < s || (so == s && ko < k)) { s = so; k = ko; }
            }
            g_idx[plist[tid]] = k;
        }
    }
}

// ---------------- kernel 6: gather/writeback (no loss, no x read) ----------
__global__ __launch_bounds__(256)
void vq_writeback_kernel(const float* __restrict__ emb,
                         float* __restrict__ out) {
    __shared__ int sidx[128];
    const int tid = threadIdx.x;
    const int pix0 = blockIdx.x * 128;
    const int b = pix0 >> 12;
    const int hw0 = pix0 & (HW - 1);

    if (tid < 128) sidx[tid] = g_idx[pix0 + tid];
    __syncthreads();

#pragma unroll 4
    for (int it = 0; it < (128 * EMB_DIM) / 256; it++) {
        int i = tid + it * 256;
        int p = i & 127;
        int c = i >> 7;
        int idx = sidx[p];
        float q = __ldg(&emb[(size_t)idx * EMB_DIM + c]);
        out[1 + ((size_t)b * EMB_DIM + c) * HW + hw0 + p] = q;
    }
}

__global__ void vq_finalize_kernel(float* __restrict__ out) {
    out[0] = (float)(g_loss * (1.0625 / 16777216.0));
}

extern "C" void kernel_launch(void* const* d_in, const int* in_sizes, int n_in,
                              void* d_out, int out_size) {
    const float* x = (const float*)d_in[0];
    const float* emb = (const float*)d_in[1];
    float* out = (float*)d_out;

    cudaFuncSetAttribute(vq_gemm_kernel,
                         cudaFuncAttributeMaxDynamicSharedMemorySize, GEMM_DSMEM);

    vq_esplit_kernel<<<NUM_EMB, 256>>>(emb);
    vq_etrans_kernel<<<EMB_DIM, 256>>>(emb);
    vq_enorm_kernel<<<NUM_EMB / 32, 256>>>(emb);
    vq_xsplit_kernel<<<NPIX / 128, 256>>>(x);
    vq_gemm_kernel<<<NPIX / 128, 256, GEMM_DSMEM>>>();
    vq_rescue_kernel<<<148, 256>>>(x);
    vq_writeback_kernel<<<NPIX / 128, 256>>>(emb, out);
    vq_finalize_kernel<<<1, 1>>>(out);
}

// round 17
// speedup vs baseline: 5.8212x; 1.0084x over previous
#include <cuda_runtime.h>
#include <cuda_bf16.h>
#include <cstdint>

// VQ-VAE quantizer: bf16 hi-only HMMA screening (K'=256, flattened 3-stage
// cp.async pipeline, ldmatrix fragments, fused loss) + exact-chain rescue
// (one pixel per block), reproducing the JAX/XLA-CPU fp32 reference argmin.
//   x: [16, 256, 64, 64] f32   (d_in[0])
//   emb: [1024, 256] f32       (d_in[1])
//   out: [1 + 16*256*64*64] f32: out[0]=c_loss, out[1:]=quant_out (NCHW)

#define NUM_EMB 1024
#define EMB_DIM 256
#define HW 4096
#define NPIX 65536
#define MARGIN 3.0e-4f
#define STAGE_B 18432           // 128 rows x 72 halves x 2B
#define GEMM_DSMEM (6 * STAGE_B)   // 3 stages A + 3 stages B = 108 KB

__device__ double g_loss;
__device__ float g_enorm[NUM_EMB];
__device__ float g_xnorm[NPIX];
__device__ int g_idx[NPIX];
__device__ int g_resc_count;
__device__ int g_resc[NPIX];
__device__ __nv_bfloat16 g_Xp[(size_t)NPIX * EMB_DIM];  // [pixel][256] hi(x)
__device__ __nv_bfloat16 g_Ep[NUM_EMB * EMB_DIM];       // [code][256] hi(e)
__device__ float g_EpT[EMB_DIM * NUM_EMB];              // [c][k] transposed emb

#define MMA16816(d, a0, a1, a2, a3, bb0, bb1) \
    asm volatile("mma.sync.aligned.m16n8k16.row.col.f32.bf16.bf16.f32 " \
                 "{%0,%1,%2,%3}, {%4,%5,%6,%7}, {%8,%9}, {%0,%1,%2,%3};" \
                 : "+f"((d)[0]), "+f"((d)[1]), "+f"((d)[2]), "+f"((d)[3]) \
                 : "r"(a0), "r"(a1), "r"(a2), "r"(a3), "r"(bb0), "r"(bb1))
#define LDSM4(r0, r1, r2, r3, addr) \
    asm volatile("ldmatrix.sync.aligned.m8n8.x4.shared.b16 {%0,%1,%2,%3}, [%4];" \
                 : "=r"(r0), "=r"(r1), "=r"(r2), "=r"(r3) : "r"(addr))
#define CPASYNC16(dst_u32, src) \
    asm volatile("cp.async.cg.shared.global [%0], [%1], 16;" \
                 :: "r"(dst_u32), "l"(src) : "memory")
#define CPCOMMIT() asm volatile("cp.async.commit_group;" ::: "memory")
#define CPWAIT1() asm volatile("cp.async.wait_group 1;" ::: "memory")
#define CPWAIT0() asm volatile("cp.async.wait_group 0;" ::: "memory")

__device__ __forceinline__ uint32_t smem_u32(const void* p) {
    uint32_t a;
    asm("{ .reg .u64 t; cvta.to.shared.u64 t, %1; cvt.u32.u64 %0, t; }" : "=r"(a) : "l"(p));
    return a;
}

// ---------------- kernel 1a: E -> bf16 hi (+ zero accumulators) -------------
__global__ void vq_esplit_kernel(const float* __restrict__ emb) {
    const int k = blockIdx.x;       // 1024 blocks
    const int c = threadIdx.x;      // 256 threads
    if (k == 0 && c == 0) { g_loss = 0.0; g_resc_count = 0; }
    float v = emb[(size_t)k * EMB_DIM + c];
    g_Ep[(size_t)k * EMB_DIM + c] = __float2bfloat16_rn(v);
}

// ---------------- kernel 1b: transpose emb -> g_EpT[c][k] -------------------
__global__ void vq_etrans_kernel(const float* __restrict__ emb) {
    const int c = blockIdx.x;       // 256 blocks
#pragma unroll
    for (int q = 0; q < 4; q++) {
        int k = threadIdx.x + q * 256;
        g_EpT[c * NUM_EMB + k] = emb[(size_t)k * EMB_DIM + c];
    }
}

// ---------------- kernel 1c: ||e_k||^2, 8 lanes/code, exact XLA tree --------
__global__ void vq_enorm_kernel(const float* __restrict__ emb) {
    const int tid = threadIdx.x;
    const int gw = (blockIdx.x * blockDim.x + tid) >> 5;
    const int lane = tid & 31;
    const int k = gw * 4 + (lane >> 3);
    const int r = lane & 7;
    const float* row = emb + (size_t)k * EMB_DIM;
    float S = 0.f;
#pragma unroll 8
    for (int j = 0; j < 32; j++) {
        float v = row[r + 8 * j];
        S = __fadd_rn(S, __fmul_rn(v, v));
    }
    float o = __shfl_down_sync(0xffffffffu, S, 4, 8);
    float T = __fadd_rn(S, o);
    o = __shfl_down_sync(0xffffffffu, T, 2, 8);
    float U = __fadd_rn(T, o);
    o = __shfl_down_sync(0xffffffffu, U, 1, 8);
    float R = __fadd_rn(U, o);
    if (r == 0) g_enorm[k] = R;
}

// ---------------- kernel 2: split X (hi only) + fused ||x||^2 --------------
__global__ __launch_bounds__(256)
void vq_xsplit_kernel(const float* __restrict__ x) {
    __shared__ float xs[128 * 66];   // [p][c], stride 66
    const int tid = threadIdx.x;
    const int pix0 = blockIdx.x * 128;
    const int b = pix0 >> 12;
    const int hw0 = pix0 & (HW - 1);
    const float* xbase = x + ((size_t)b * EMB_DIM) * HW + hw0;
    const int r = tid & 7;

    float S4[4];
#pragma unroll
    for (int sl = 0; sl < 4; sl++) S4[sl] = 0.f;

    for (int c0 = 0; c0 < EMB_DIM; c0 += 64) {
        __syncthreads();
#pragma unroll
        for (int it = 0; it < 32; it++) {
            int i = tid + it * 256;
            int p = i & 127, c = i >> 7;
            xs[p * 66 + c] = xbase[(size_t)(c0 + c) * HW + p];
        }
        __syncthreads();
#pragma unroll
        for (int it = 0; it < 16; it++) {
            int i = tid + it * 256;
            int p = i >> 5, cp = i & 31;
            float2 v = *(const float2*)&xs[p * 66 + 2 * cp];
            __nv_bfloat162 hh;
            hh.x = __float2bfloat16_rn(v.x);
            hh.y = __float2bfloat16_rn(v.y);
            *(__nv_bfloat162*)&g_Xp[(size_t)(pix0 + p) * EMB_DIM + c0 + 2 * cp] = hh;
        }
#pragma unroll
        for (int sl = 0; sl < 4; sl++) {
            int p = (tid >> 3) + 32 * sl;
            const float* row = &xs[p * 66];
#pragma unroll
            for (int j = 0; j < 8; j++) {
                float v = row[r + 8 * j];
                S4[sl] = __fadd_rn(S4[sl], __fmul_rn(v, v));
            }
        }
    }
#pragma unroll
    for (int sl = 0; sl < 4; sl++) {
        float S = S4[sl];
        float o = __shfl_down_sync(0xffffffffu, S, 4, 8);
        float T = __fadd_rn(S, o);
        o = __shfl_down_sync(0xffffffffu, T, 2, 8);
        float U = __fadd_rn(T, o);
        o = __shfl_down_sync(0xffffffffu, U, 1, 8);
        float R = __fadd_rn(U, o);
        if (r == 0) g_xnorm[pix0 + (tid >> 3) + 32 * sl] = R;
    }
}

// ---------------- kernel 4: HMMA GEMM screening + argmin + fused loss ------
__global__ __launch_bounds__(256, 2)
void vq_gemm_kernel() {
    extern __shared__ __align__(16) char dsm[];
    __nv_bfloat16* As = (__nv_bfloat16*)dsm;                    // 3 stages
    __nv_bfloat16* Bs = (__nv_bfloat16*)(dsm + 3 * STAGE_B);    // 3 stages
    __shared__ float mb1[128];
    __shared__ float mb2[128];
    __shared__ int mi1s[128];
    __shared__ float s_lsum;

    const int tid = threadIdx.x;
    const int lane = tid & 31;
    const int wid = tid >> 5;
    const int wm = wid & 3;
    const int wn = wid >> 2;
    const int g = lane >> 2;
    const int t = lane & 3;
    const int pix0 = blockIdx.x * 128;

    if (tid == 0) s_lsum = 0.f;

    const uint32_t sA = smem_u32(As);
    const uint32_t sB = smem_u32(Bs);
    const char* XpB = (const char*)g_Xp;
    const char* EpB = (const char*)g_Ep;

    const int lh = lane & 7;
    const int l8 = (lane >> 3) & 1;
    const int l16 = (lane >> 4) & 1;
    const uint32_t aoff = (uint32_t)((32 * wm + lh + 8 * l8) * 144 + l16 * 16);
    const uint32_t boff = (uint32_t)((64 * wn + lh + 8 * l16) * 144 + l8 * 16);

    int frow[4], fcj[4];
#pragma unroll
    for (int it = 0; it < 4; it++) {
        int id = tid + it * 256;
        frow[it] = id >> 3;
        fcj[it] = id & 7;
    }

    float a_p[4];
    int rowOf[4];
#pragma unroll
    for (int s = 0; s < 4; s++) {
        rowOf[s] = 32 * wm + 16 * (s >> 1) + 8 * (s & 1) + g;
        a_p[s] = g_xnorm[pix0 + rowOf[s]];
    }
    float b1[4], b2[4];
    int i1[4];
#pragma unroll
    for (int s = 0; s < 4; s++) { b1[s] = 3.4e38f; b2[s] = 3.4e38f; i1[s] = 0; }

    float acc[2][8][4];

    // prologue: prefetch chunks 0, 1 (tile 0, kc 0/1)
#pragma unroll
    for (int m = 0; m < 2; m++) {
#pragma unroll
        for (int it = 0; it < 4; it++) {
            uint32_t doff = (uint32_t)(m * STAGE_B + frow[it] * 144 + fcj[it] * 16);
            size_t koff = (size_t)m * 64 + fcj[it] * 8;
            CPASYNC16(sA + doff, XpB + ((size_t)(pix0 + frow[it]) * EMB_DIM + koff) * 2);
            CPASYNC16(sB + doff, EpB + ((size_t)frow[it] * EMB_DIM + koff) * 2);
        }
        CPCOMMIT();
    }

    for (int m = 0; m < 32; m++) {
        const int kc = m & 3;
        const uint32_t stB = (uint32_t)((m % 3) * STAGE_B);

        if (kc == 0) {
#pragma unroll
            for (int mi = 0; mi < 2; mi++)
#pragma unroll
                for (int ni = 0; ni < 8; ni++)
#pragma unroll
                    for (int q = 0; q < 4; q++) acc[mi][ni][q] = 0.f;
        }

        if (m == 31) { CPWAIT0(); } else { CPWAIT1(); }
        __syncthreads();

#pragma unroll
        for (int kf = 0; kf < 4; kf++) {
            uint32_t a[2][4];
#pragma unroll
            for (int mi = 0; mi < 2; mi++)
                LDSM4(a[mi][0], a[mi][1], a[mi][2], a[mi][3],
                      sA + stB + aoff + (uint32_t)(mi * 2304 + kf * 32));
#pragma unroll
            for (int np = 0; np < 4; np++) {
                uint32_t bb0, bb1, bb2, bb3;
                LDSM4(bb0, bb1, bb2, bb3,
                      sB + stB + boff + (uint32_t)(np * 2304 + kf * 32));
#pragma unroll
                for (int mi = 0; mi < 2; mi++) {
                    MMA16816(acc[mi][2 * np], a[mi][0], a[mi][1], a[mi][2], a[mi][3], bb0, bb1);
                    MMA16816(acc[mi][2 * np + 1], a[mi][0], a[mi][1], a[mi][2], a[mi][3], bb2, bb3);
                }
            }
        }

        if (m + 2 < 32) {
            const int m2 = m + 2;
            const int tile2 = m2 >> 2, kc2 = m2 & 3;
            const uint32_t st2 = (uint32_t)((m2 % 3) * STAGE_B);
#pragma unroll
            for (int it = 0; it < 4; it++) {
                uint32_t doff = st2 + (uint32_t)(frow[it] * 144 + fcj[it] * 16);
                size_t koff = (size_t)kc2 * 64 + fcj[it] * 8;
                CPASYNC16(sA + doff, XpB + ((size_t)(pix0 + frow[it]) * EMB_DIM + koff) * 2);
                CPASYNC16(sB + doff, EpB + ((size_t)(tile2 * 128 + frow[it]) * EMB_DIM + koff) * 2);
            }
            CPCOMMIT();
        }

        if (kc == 3) {
            // Epilogue: reference-rounded scores.
            // c-frag: q0=(g,2t) q1=(g,2t+1) q2=(g+8,2t) q3=(g+8,2t+1); s=2mi+(q>>1).
            const int n0 = (m >> 2) * 128;
#pragma unroll
            for (int ni = 0; ni < 8; ni++) {
                int kb = n0 + 64 * wn + 8 * ni + 2 * t;
                float c0 = __ldg(&g_enorm[kb]);
                float c1 = __ldg(&g_enorm[kb + 1]);
#pragma unroll
                for (int mi = 0; mi < 2; mi++) {
#pragma unroll
                    for (int q = 0; q < 4; q++) {
                        int s = 2 * mi + (q >> 1);
                        float bv = acc[mi][ni][q];
                        int k = kb + (q & 1);
                        float cn = (q & 1) ? c1 : c0;
                        float sc = __fadd_rn(__fsub_rn(a_p[s], __fmul_rn(2.0f, bv)), cn);
                        if (sc < b1[s]) { b2[s] = b1[s]; b1[s] = sc; i1[s] = k; }
                        else if (sc < b2[s]) { b2[s] = sc; }
                    }
                }
            }
        }
    }

#pragma unroll
    for (int s = 0; s < 4; s++) {
        float x1 = b1[s], x2 = b2[s];
        int xi = i1[s];
#pragma unroll
        for (int off = 2; off > 0; off >>= 1) {
            float o1 = __shfl_down_sync(0xffffffffu, x1, off, 4);
            float o2 = __shfl_down_sync(0xffffffffu, x2, off, 4);
            int oi = __shfl_down_sync(0xffffffffu, xi, off, 4);
            float n2 = fminf(fmaxf(x1, o1), fminf(x2, o2));
            if (o1 < x1 || (o1 == x1 && oi < xi)) { x1 = o1; xi = oi; }
            x2 = n2;
        }
        b1[s] = x1; b2[s] = x2; i1[s] = xi;
    }
    if (wn == 0 && t == 0) {
#pragma unroll
        for (int s = 0; s < 4; s++) {
            mb1[rowOf[s]] = b1[s];
            mb2[rowOf[s]] = b2[s];
            mi1s[rowOf[s]] = i1[s];
        }
    }
    __syncthreads();
    if (wn == 1 && t == 0) {
        float ls = 0.f;
#pragma unroll
        for (int s = 0; s < 4; s++) {
            int r = rowOf[s];
            float o1 = mb1[r], o2 = mb2[r];
            int oi = mi1s[r];
            float n2 = fminf(fmaxf(b1[s], o1), fminf(b2[s], o2));
            float n1;
            int ni_;
            if (o1 < b1[s] || (o1 == b1[s] && oi < i1[s])) { n1 = o1; ni_ = oi; }
            else { n1 = b1[s]; ni_ = i1[s]; }
            int p = pix0 + r;
            g_idx[p] = ni_;
            ls += n1;                       // score = ||x - q||^2 (loss term)
            if (n2 - n1 < MARGIN) {
                int rr = atomicAdd(&g_resc_count, 1);
                g_resc[rr] = p;
            }
        }
        atomicAdd(&s_lsum, ls);
    }
    __syncthreads();
    if (tid == 0) atomicAdd(&g_loss, (double)s_lsum);
}

// ---------------- kernel 5: exact rescue, ONE pixel per block --------------
// Per-(pixel,code) fp32 chain: strictly sequential over ascending c (Eigen
// order), identical rounding ops -> bitwise reference scores. Thread owns
// codes tid+256q, visited ascending; lexicographic (score,k) min == the
// reference first-index rule (all k distinct).
__global__ __launch_bounds__(256)
void vq_rescue_kernel(const float* __restrict__ x) {
    __shared__ float xsm[EMB_DIM];
    __shared__ float rbs[8];
    __shared__ int rbk[8];
    const int tid = threadIdx.x;
    const int lane = tid & 31, wid = tid >> 5;
    const int cnt = g_resc_count;

    for (int r = blockIdx.x; r < cnt; r += gridDim.x) {
        const int p = g_resc[r];
        const int b = p >> 12, hw = p & (HW - 1);
        __syncthreads();
        xsm[tid] = x[((size_t)b * EMB_DIM + tid) * HW + hw];
        __syncthreads();
        const float a = g_xnorm[p];

        float acc[4];
#pragma unroll
        for (int q = 0; q < 4; q++) acc[q] = 0.f;
        for (int c = 0; c < EMB_DIM; c++) {
            float xv = xsm[c];
            const float* ept = &g_EpT[c * NUM_EMB + tid];
#pragma unroll
            for (int q = 0; q < 4; q++)
                acc[q] = fmaf(xv, ept[q * 256], acc[q]);
        }
        float bs = 3.4e38f;
        int bk = 0;
#pragma unroll
        for (int q = 0; q < 4; q++) {
            int k = tid + q * 256;
            float s = __fadd_rn(__fsub_rn(a, __fmul_rn(2.0f, acc[q])), g_enorm[k]);
            if (s < bs) { bs = s; bk = k; }
        }
#pragma unroll
        for (int off = 16; off > 0; off >>= 1) {
            float so = __shfl_down_sync(0xffffffffu, bs, off);
            int ko = __shfl_down_sync(0xffffffffu, bk, off);
            if (so < bs || (so == bs && ko < bk)) { bs = so; bk = ko; }
        }
        if (lane == 0) { rbs[wid] = bs; rbk[wid] = bk; }
        __syncthreads();
        if (tid == 0) {
            float s = rbs[0];
            int k = rbk[0];
#pragma unroll
            for (int w = 1; w < 8; w++) {
                if (rbs[w] < s || (rbs[w] == s && rbk[w] < k)) { s = rbs[w]; k = rbk[w]; }
            }
            g_idx[p] = k;
        }
    }
}

// ---------------- kernel 6: gather/writeback (no loss, no x read) ----------
__global__ __launch_bounds__(256)
void vq_writeback_kernel(const float* __restrict__ emb,
                         float* __restrict__ out) {
    __shared__ int sidx[128];
    const int tid = threadIdx.x;
    const int pix0 = blockIdx.x * 128;
    const int b = pix0 >> 12;
    const int hw0 = pix0 & (HW - 1);

    if (tid < 128) sidx[tid] = g_idx[pix0 + tid];
    __syncthreads();

#pragma unroll 4
    for (int it = 0; it < (128 * EMB_DIM) / 256; it++) {
        int i = tid + it * 256;
        int p = i & 127;
        int c = i >> 7;
        int idx = sidx[p];
        float q = __ldg(&emb[(size_t)idx * EMB_DIM + c]);
        out[1 + ((size_t)b * EMB_DIM + c) * HW + hw0 + p] = q;
    }
}

__global__ void vq_finalize_kernel(float* __restrict__ out) {
    out[0] = (float)(g_loss * (1.0625 / 16777216.0));
}

extern "C" void kernel_launch(void* const* d_in, const int* in_sizes, int n_in,
                              void* d_out, int out_size) {
    const float* x = (const float*)d_in[0];
    const float* emb = (const float*)d_in[1];
    float* out = (float*)d_out;

    cudaFuncSetAttribute(vq_gemm_kernel,
                         cudaFuncAttributeMaxDynamicSharedMemorySize, GEMM_DSMEM);

    vq_esplit_kernel<<<NUM_EMB, 256>>>(emb);
    vq_etrans_kernel<<<EMB_DIM, 256>>>(emb);
    vq_enorm_kernel<<<NUM_EMB / 32, 256>>>(emb);
    vq_xsplit_kernel<<<NPIX / 128, 256>>>(x);
    vq_gemm_kernel<<<NPIX / 128, 256, GEMM_DSMEM>>>();
    vq_rescue_kernel<<<2048, 256>>>(x);
    vq_writeback_kernel<<<NPIX / 128, 256>>>(emb, out);
    vq_finalize_kernel<<<1, 1>>>(out);
}